// round 5
// baseline (speedup 1.0000x reference)
#include <cuda_runtime.h>

// Problem constants (fixed by the dataset)
#define NN    50000      // nodes
#define NE    1600000    // edges
#define FIN   512        // input features
#define DIMF  512        // hidden dim
#define NCLS  40         // classes
#define HDIM  2048       // H = [ t(512) | s1(512) | t2(1024) ]

// ---------------- scratch (device globals: no cudaMalloc allowed) ----------
__device__ __align__(128) float g_H[(size_t)NN * HDIM];   // ~410 MB
__device__ __align__(128) float g_Wc[HDIM * NCLS];        // combined W2
__device__ float g_dinv[NN];
__device__ int   g_degc[NN];
__device__ int   g_rcnt[NN];
__device__ int   g_rowptr[NN + 1];
__device__ int   g_cursor[NN];
__device__ int   g_cols[NE];

// ---------------- graph preprocessing ---------------------------------------
__global__ void k_zero_counts() {
    int i = blockIdx.x * blockDim.x + threadIdx.x;
    if (i < NN) { g_degc[i] = 0; g_rcnt[i] = 0; g_cursor[i] = 0; }
}

__global__ void k_count(const int* __restrict__ erow, const int* __restrict__ ecol) {
    int e = blockIdx.x * blockDim.x + threadIdx.x;
    if (e < NE) {
        atomicAdd(&g_degc[ecol[e]], 1);
        atomicAdd(&g_rcnt[erow[e]], 1);
    }
}

__global__ void k_dinv() {
    int i = blockIdx.x * blockDim.x + threadIdx.x;
    if (i < NN) g_dinv[i] = rsqrtf((float)(g_degc[i] + 1));  // +1 self loop
}

// single-block exclusive scan of g_rcnt -> g_rowptr
__global__ void __launch_bounds__(1024) k_scan() {
    __shared__ int sh[1024];
    __shared__ int carry;
    if (threadIdx.x == 0) { carry = 0; g_rowptr[0] = 0; }
    __syncthreads();
    for (int base = 0; base < NN; base += 1024) {
        int i = base + threadIdx.x;
        int v = (i < NN) ? g_rcnt[i] : 0;
        sh[threadIdx.x] = v;
        __syncthreads();
        for (int off = 1; off < 1024; off <<= 1) {
            int t = (threadIdx.x >= off) ? sh[threadIdx.x - off] : 0;
            __syncthreads();
            sh[threadIdx.x] += t;
            __syncthreads();
        }
        if (i < NN) g_rowptr[i + 1] = carry + sh[threadIdx.x];
        __syncthreads();
        if (threadIdx.x == 0) carry += sh[1023];
        __syncthreads();
    }
}

__global__ void k_scatter(const int* __restrict__ erow, const int* __restrict__ ecol) {
    int e = blockIdx.x * blockDim.x + threadIdx.x;
    if (e < NE) {
        int r = erow[e];
        int p = g_rowptr[r] + atomicAdd(&g_cursor[r], 1);
        g_cols[p] = ecol[e];
    }
}

// Combined classifier weight:
// h = [t, t, s1, t2] @ W2  ==  [t, s1, t2] @ Wc  with
// Wc[0:512]   = W2[0:512] + W2[512:1024]
// Wc[512:2048]= W2[1024:2560]
__global__ void k_wc(const float* __restrict__ W2) {
    int i = blockIdx.x * blockDim.x + threadIdx.x;
    const int S = 512 * NCLS;
    if (i < S)               g_Wc[i] = W2[i] + W2[i + S];
    else if (i < HDIM * NCLS) g_Wc[i] = W2[i + S];
}

// ---------------- GEMM1: t = relu(x @ W1 + b1) -> H[:, 0:512] ---------------
// 128x128 tile, BK=16, 8x8 per thread, 256 threads.
__global__ void __launch_bounds__(256) k_gemm1(const float* __restrict__ A,
                                               const float* __restrict__ B,
                                               const float* __restrict__ bias) {
    __shared__ float As[16][128];
    __shared__ float Bs[16][128];
    int bm = blockIdx.y * 128;
    int bn = blockIdx.x * 128;
    int tid = threadIdx.x;
    int tx = tid & 15, ty = tid >> 4;

    float acc[8][8];
#pragma unroll
    for (int i = 0; i < 8; i++)
#pragma unroll
        for (int j = 0; j < 8; j++) acc[i][j] = 0.f;

    for (int k0 = 0; k0 < FIN; k0 += 16) {
#pragma unroll
        for (int l = 0; l < 2; l++) {
            int i = tid + l * 256;
            // A tile: 128 rows x 16 k  (transposed into As[k][row])
            int r = i >> 2, kk = (i & 3) * 4;
            float4 av = make_float4(0.f, 0.f, 0.f, 0.f);
            int gr = bm + r;
            if (gr < NN) av = *(const float4*)(A + (size_t)gr * FIN + k0 + kk);
            As[kk + 0][r] = av.x; As[kk + 1][r] = av.y;
            As[kk + 2][r] = av.z; As[kk + 3][r] = av.w;
            // B tile: 16 rows x 128 cols
            int br = i >> 5, bc = (i & 31) * 4;
            *(float4*)&Bs[br][bc] =
                *(const float4*)(B + (size_t)(k0 + br) * DIMF + bn + bc);
        }
        __syncthreads();
#pragma unroll
        for (int k = 0; k < 16; k++) {
            float a[8], b[8];
            *(float4*)&a[0] = *(const float4*)&As[k][ty * 8];
            *(float4*)&a[4] = *(const float4*)&As[k][ty * 8 + 4];
            *(float4*)&b[0] = *(const float4*)&Bs[k][tx * 8];
            *(float4*)&b[4] = *(const float4*)&Bs[k][tx * 8 + 4];
#pragma unroll
            for (int i = 0; i < 8; i++)
#pragma unroll
                for (int j = 0; j < 8; j++) acc[i][j] = fmaf(a[i], b[j], acc[i][j]);
        }
        __syncthreads();
    }
#pragma unroll
    for (int i = 0; i < 8; i++) {
        int gr = bm + ty * 8 + i;
        if (gr < NN) {
#pragma unroll
            for (int j = 0; j < 8; j += 4) {
                int gc = bn + tx * 8 + j;
                float4 o;
                o.x = fmaxf(acc[i][j + 0] + bias[gc + 0], 0.f);
                o.y = fmaxf(acc[i][j + 1] + bias[gc + 1], 0.f);
                o.z = fmaxf(acc[i][j + 2] + bias[gc + 2], 0.f);
                o.w = fmaxf(acc[i][j + 3] + bias[gc + 3], 0.f);
                *(float4*)&g_H[(size_t)gr * HDIM + gc] = o;
            }
        }
    }
}

// ---------------- SpMM: out[r] = dinv[r]*(sum_c dinv[c]*in[c] + dinv[r]*in[r])
// One block per row, blockDim = F/4 threads, float4 per thread.
template <int INOFF, int OUTOFF, int F>
__global__ void k_spmm() {
    int r = blockIdx.x;
    int f = threadIdx.x * 4;
    float di = g_dinv[r];
    const float* __restrict__ H = g_H;

    float4 sv = *(const float4*)&H[(size_t)r * HDIM + INOFF + f];
    float4 acc;
    acc.x = di * sv.x; acc.y = di * sv.y; acc.z = di * sv.z; acc.w = di * sv.w;

    int s = g_rowptr[r], e = g_rowptr[r + 1];
    int j = s;
    for (; j + 1 < e; j += 2) {
        int c0 = g_cols[j];
        int c1 = g_cols[j + 1];
        float w0 = g_dinv[c0];
        float w1 = g_dinv[c1];
        float4 v0 = *(const float4*)&H[(size_t)c0 * HDIM + INOFF + f];
        float4 v1 = *(const float4*)&H[(size_t)c1 * HDIM + INOFF + f];
        acc.x = fmaf(w0, v0.x, fmaf(w1, v1.x, acc.x));
        acc.y = fmaf(w0, v0.y, fmaf(w1, v1.y, acc.y));
        acc.z = fmaf(w0, v0.z, fmaf(w1, v1.z, acc.z));
        acc.w = fmaf(w0, v0.w, fmaf(w1, v1.w, acc.w));
    }
    if (j < e) {
        int c0 = g_cols[j];
        float w0 = g_dinv[c0];
        float4 v0 = *(const float4*)&H[(size_t)c0 * HDIM + INOFF + f];
        acc.x = fmaf(w0, v0.x, acc.x);
        acc.y = fmaf(w0, v0.y, acc.y);
        acc.z = fmaf(w0, v0.z, acc.z);
        acc.w = fmaf(w0, v0.w, acc.w);
    }
    acc.x *= di; acc.y *= di; acc.z *= di; acc.w *= di;
    *(float4*)&g_H[(size_t)r * HDIM + OUTOFF + f] = acc;
}

// ---------------- GEMM2: logits = H @ Wc + b2  -> d_out ---------------------
// 64 rows x 40 cols per block, 320 threads (col = tid%40, 8 rows each).
__global__ void __launch_bounds__(320) k_gemm2(const float* __restrict__ bias,
                                               float* __restrict__ out) {
    __shared__ float Hs[64][36];   // pad to 36 (mult of 4, offset-breaking)
    __shared__ float Wt[40][36];   // transposed: Wt[c][k]
    int bm = blockIdx.x * 64;
    int tid = threadIdx.x;
    int col = tid % 40;
    int rg = tid / 40;             // 0..7, handles rows rg*8 .. rg*8+7

    float acc[8];
#pragma unroll
    for (int i = 0; i < 8; i++) acc[i] = 0.f;

    for (int k0 = 0; k0 < HDIM; k0 += 32) {
        for (int i = tid; i < 32 * 40; i += 320) {
            // flat i = k*40 + c; coalesced read of g_Wc
            Wt[i % 40][i / 40] = g_Wc[k0 * 40 + i];
        }
        for (int i = tid; i < 512; i += 320) {
            int r = i >> 3, kk = (i & 7) << 2;
            float4 v = make_float4(0.f, 0.f, 0.f, 0.f);
            if (bm + r < NN)
                v = *(const float4*)&g_H[(size_t)(bm + r) * HDIM + k0 + kk];
            Hs[r][kk + 0] = v.x; Hs[r][kk + 1] = v.y;
            Hs[r][kk + 2] = v.z; Hs[r][kk + 3] = v.w;
        }
        __syncthreads();
#pragma unroll
        for (int k = 0; k < 32; k += 4) {
            float4 w = *(const float4*)&Wt[col][k];
#pragma unroll
            for (int i = 0; i < 8; i++) {
                float4 h = *(const float4*)&Hs[rg * 8 + i][k];
                acc[i] = fmaf(h.x, w.x, acc[i]);
                acc[i] = fmaf(h.y, w.y, acc[i]);
                acc[i] = fmaf(h.z, w.z, acc[i]);
                acc[i] = fmaf(h.w, w.w, acc[i]);
            }
        }
        __syncthreads();
    }
    float b = bias[col];
#pragma unroll
    for (int i = 0; i < 8; i++) {
        int gr = bm + rg * 8 + i;
        if (gr < NN) out[(size_t)gr * NCLS + col] = acc[i] + b;
    }
}

// ---------------- log_softmax in-place on [NN, 40], one warp per row --------
__global__ void k_logsoftmax(float* __restrict__ out) {
    int gt = blockIdx.x * blockDim.x + threadIdx.x;
    int r = gt >> 5;
    int lane = gt & 31;
    if (r >= NN) return;
    float* p = out + (size_t)r * NCLS;
    float v0 = p[lane];
    float v1 = (lane < 8) ? p[32 + lane] : -1e30f;
    float m = fmaxf(v0, v1);
#pragma unroll
    for (int o = 16; o; o >>= 1) m = fmaxf(m, __shfl_xor_sync(0xffffffffu, m, o));
    float s = expf(v0 - m) + ((lane < 8) ? expf(v1 - m) : 0.f);
#pragma unroll
    for (int o = 16; o; o >>= 1) s += __shfl_xor_sync(0xffffffffu, s, o);
    float lse = m + logf(s);
    p[lane] = v0 - lse;
    if (lane < 8) p[32 + lane] = v1 - lse;
}

// ---------------- entry -----------------------------------------------------
extern "C" void kernel_launch(void* const* d_in, const int* in_sizes, int n_in,
                              void* d_out, int out_size) {
    const float* x    = (const float*)d_in[0];
    const int*   erow = (const int*)d_in[1];
    const int*   ecol = (const int*)d_in[2];
    const float* W1   = (const float*)d_in[3];
    const float* b1   = (const float*)d_in[4];
    const float* W2   = (const float*)d_in[5];
    const float* b2   = (const float*)d_in[6];
    float* out = (float*)d_out;
    (void)in_sizes; (void)n_in; (void)out_size;

    // graph preprocessing
    k_zero_counts<<<(NN + 255) / 256, 256>>>();
    k_count<<<(NE + 255) / 256, 256>>>(erow, ecol);
    k_dinv<<<(NN + 255) / 256, 256>>>();
    k_scan<<<1, 1024>>>();
    k_scatter<<<(NE + 255) / 256, 256>>>(erow, ecol);
    k_wc<<<(HDIM * NCLS + 255) / 256, 256>>>(W2);

    // t = relu(x @ W1 + b1)  -> H[:,0:512]
    dim3 g1(DIMF / 128, (NN + 127) / 128);
    k_gemm1<<<g1, 256>>>(x, W1, b1);

    // s1 = spmm(t)           -> H[:,512:1024]
    k_spmm<0, 512, 512><<<NN, 128>>>();
    // t2 = spmm([t,s1])      -> H[:,1024:2048]
    k_spmm<0, 1024, 1024><<<NN, 256>>>();

    // logits = H @ Wc + b2
    k_gemm2<<<(NN + 63) / 64, 320>>>(b2, out);

    // log_softmax in-place
    int warps = NN;
    k_logsoftmax<<<(warps * 32 + 255) / 256, 256>>>(out);
}

// round 6
// speedup vs baseline: 1.3756x; 1.3756x over previous
#include <cuda_runtime.h>

// Problem constants (fixed by the dataset)
#define NN    50000      // nodes
#define NE    1600000    // edges
#define FIN   512        // input features
#define DIMF  512        // hidden dim
#define NCLS  40         // classes
#define HDIM  1536       // H = [ t(512) | s1(512) | s2(512) ]

// ---------------- scratch (device globals: no cudaMalloc allowed) ----------
__device__ __align__(128) float g_H[(size_t)NN * HDIM];   // ~307 MB
__device__ __align__(128) float g_Wc[HDIM * NCLS];        // combined W2
__device__ float g_dinv[NN];
__device__ int   g_degc[NN];
__device__ int   g_rcnt[NN];
__device__ int   g_rowptr[NN + 1];
__device__ int   g_cursor[NN];
__device__ int   g_cols[NE];

// ---------------- f32x2 packed-FMA helpers ----------------------------------
__device__ __forceinline__ unsigned long long pk2(float x, float y) {
    unsigned long long r;
    asm("mov.b64 %0, {%1,%2};" : "=l"(r) : "f"(x), "f"(y));
    return r;
}
__device__ __forceinline__ unsigned long long dup2(float x) {
    unsigned long long r;
    asm("mov.b64 %0, {%1,%1};" : "=l"(r) : "f"(x));
    return r;
}
__device__ __forceinline__ void upk2(unsigned long long v, float& x, float& y) {
    asm("mov.b64 {%0,%1}, %2;" : "=f"(x), "=f"(y) : "l"(v));
}
__device__ __forceinline__ void ffma2(unsigned long long& d,
                                      unsigned long long a,
                                      unsigned long long b) {
    asm("fma.rn.f32x2 %0, %1, %2, %0;" : "+l"(d) : "l"(a), "l"(b));
}

// ---------------- graph preprocessing ---------------------------------------
__global__ void k_zero_counts() {
    int i = blockIdx.x * blockDim.x + threadIdx.x;
    if (i < NN) { g_degc[i] = 0; g_rcnt[i] = 0; g_cursor[i] = 0; }
}

__global__ void k_count(const int* __restrict__ erow, const int* __restrict__ ecol) {
    int e = blockIdx.x * blockDim.x + threadIdx.x;
    if (e < NE) {
        atomicAdd(&g_degc[ecol[e]], 1);
        atomicAdd(&g_rcnt[erow[e]], 1);
    }
}

__global__ void k_dinv() {
    int i = blockIdx.x * blockDim.x + threadIdx.x;
    if (i < NN) g_dinv[i] = rsqrtf((float)(g_degc[i] + 1));  // +1 self loop
}

// single-block exclusive scan of g_rcnt -> g_rowptr (warp-shuffle based)
__global__ void __launch_bounds__(1024) k_scan() {
    __shared__ int wsum[32];
    int lane = threadIdx.x & 31, wid = threadIdx.x >> 5;
    if (threadIdx.x == 0) g_rowptr[0] = 0;
    int carry = 0;
    for (int base = 0; base < NN; base += 1024) {
        int i = base + threadIdx.x;
        int s = (i < NN) ? g_rcnt[i] : 0;
#pragma unroll
        for (int o = 1; o < 32; o <<= 1) {
            int t = __shfl_up_sync(0xffffffffu, s, o);
            if (lane >= o) s += t;
        }
        if (lane == 31) wsum[wid] = s;
        __syncthreads();
        if (wid == 0) {
            int ws = wsum[lane];
#pragma unroll
            for (int o = 1; o < 32; o <<= 1) {
                int t = __shfl_up_sync(0xffffffffu, ws, o);
                if (lane >= o) ws += t;
            }
            wsum[lane] = ws;
        }
        __syncthreads();
        int off = carry + (wid > 0 ? wsum[wid - 1] : 0);
        if (i < NN) g_rowptr[i + 1] = off + s;
        carry += wsum[31];
        __syncthreads();
    }
}

__global__ void k_scatter(const int* __restrict__ erow, const int* __restrict__ ecol) {
    int e = blockIdx.x * blockDim.x + threadIdx.x;
    if (e < NE) {
        int r = erow[e];
        int p = g_rowptr[r] + atomicAdd(&g_cursor[r], 1);
        g_cols[p] = ecol[e];
    }
}

// Combined classifier weight over [t(512) | s1(512) | s2(512)]:
// h = [t, t, s1, s1, s2] @ W2  ==  [t, s1, s2] @ Wc  with
//   Wc[0:512]     = W2[0:512]    + W2[512:1024]
//   Wc[512:1024]  = W2[1024:1536]+ W2[1536:2048]
//   Wc[1024:1536] = W2[2048:2560]
__global__ void k_wc(const float* __restrict__ W2) {
    int i = blockIdx.x * blockDim.x + threadIdx.x;
    const int S = 512 * NCLS;
    if (i < S)                      g_Wc[i] = W2[i] + W2[i + S];
    else if (i < 2 * S)             g_Wc[i] = W2[i + S] + W2[i + 2 * S];
    else if (i < HDIM * NCLS)       g_Wc[i] = W2[i + 2 * S];
}

// ---------------- GEMM1: t = relu(x @ W1 + b1) -> H[:, 0:512] ---------------
// 128x128 tile, BK=16, 8x8 per thread, 256 threads, packed f32x2 FMAs.
__global__ void __launch_bounds__(256) k_gemm1(const float* __restrict__ A,
                                               const float* __restrict__ B,
                                               const float* __restrict__ bias) {
    __shared__ float As[16][128];
    __shared__ float Bs[16][128];
    int bm = blockIdx.y * 128;
    int bn = blockIdx.x * 128;
    int tid = threadIdx.x;
    int tx = tid & 15, ty = tid >> 4;

    unsigned long long acc2[8][4];
#pragma unroll
    for (int i = 0; i < 8; i++)
#pragma unroll
        for (int j = 0; j < 4; j++) acc2[i][j] = 0ULL;  // {0.f, 0.f}

    for (int k0 = 0; k0 < FIN; k0 += 16) {
#pragma unroll
        for (int l = 0; l < 2; l++) {
            int i = tid + l * 256;
            // A tile: 128 rows x 16 k  (transposed into As[k][row])
            int r = i >> 2, kk = (i & 3) * 4;
            float4 av = make_float4(0.f, 0.f, 0.f, 0.f);
            int gr = bm + r;
            if (gr < NN) av = *(const float4*)(A + (size_t)gr * FIN + k0 + kk);
            As[kk + 0][r] = av.x; As[kk + 1][r] = av.y;
            As[kk + 2][r] = av.z; As[kk + 3][r] = av.w;
            // B tile: 16 rows x 128 cols
            int br = i >> 5, bc = (i & 31) * 4;
            *(float4*)&Bs[br][bc] =
                *(const float4*)(B + (size_t)(k0 + br) * DIMF + bn + bc);
        }
        __syncthreads();
#pragma unroll
        for (int k = 0; k < 16; k++) {
            float4 a0 = *(const float4*)&As[k][ty * 8];
            float4 a1 = *(const float4*)&As[k][ty * 8 + 4];
            float4 b0 = *(const float4*)&Bs[k][tx * 8];
            float4 b1 = *(const float4*)&Bs[k][tx * 8 + 4];
            unsigned long long bp[4];
            bp[0] = pk2(b0.x, b0.y); bp[1] = pk2(b0.z, b0.w);
            bp[2] = pk2(b1.x, b1.y); bp[3] = pk2(b1.z, b1.w);
            unsigned long long ad[8];
            ad[0] = dup2(a0.x); ad[1] = dup2(a0.y);
            ad[2] = dup2(a0.z); ad[3] = dup2(a0.w);
            ad[4] = dup2(a1.x); ad[5] = dup2(a1.y);
            ad[6] = dup2(a1.z); ad[7] = dup2(a1.w);
#pragma unroll
            for (int i = 0; i < 8; i++)
#pragma unroll
                for (int jp = 0; jp < 4; jp++) ffma2(acc2[i][jp], ad[i], bp[jp]);
        }
        __syncthreads();
    }
#pragma unroll
    for (int i = 0; i < 8; i++) {
        int gr = bm + ty * 8 + i;
        if (gr < NN) {
#pragma unroll
            for (int jp = 0; jp < 4; jp += 2) {
                int gc = bn + tx * 8 + jp * 2;
                float4 o;
                upk2(acc2[i][jp + 0], o.x, o.y);
                upk2(acc2[i][jp + 1], o.z, o.w);
                o.x = fmaxf(o.x + bias[gc + 0], 0.f);
                o.y = fmaxf(o.y + bias[gc + 1], 0.f);
                o.z = fmaxf(o.z + bias[gc + 2], 0.f);
                o.w = fmaxf(o.w + bias[gc + 3], 0.f);
                *(float4*)&g_H[(size_t)gr * HDIM + gc] = o;
            }
        }
    }
}

// ---------------- SpMM: out[r] = dinv[r]*(sum_c dinv[c]*in[c] + dinv[r]*in[r])
// F=512, one block per row, 128 threads, float4 per thread, 4-way unroll.
template <int INOFF, int OUTOFF>
__global__ void __launch_bounds__(128) k_spmm() {
    int r = blockIdx.x;
    int f = threadIdx.x * 4;
    float di = g_dinv[r];
    const float* __restrict__ H = g_H;

    float4 sv = *(const float4*)&H[(size_t)r * HDIM + INOFF + f];
    float4 acc;
    acc.x = di * sv.x; acc.y = di * sv.y; acc.z = di * sv.z; acc.w = di * sv.w;

    int s = g_rowptr[r], e = g_rowptr[r + 1];
    int j = s;
    for (; j + 3 < e; j += 4) {
        int c0 = g_cols[j], c1 = g_cols[j + 1];
        int c2 = g_cols[j + 2], c3 = g_cols[j + 3];
        float w0 = g_dinv[c0], w1 = g_dinv[c1];
        float w2 = g_dinv[c2], w3 = g_dinv[c3];
        float4 v0 = *(const float4*)&H[(size_t)c0 * HDIM + INOFF + f];
        float4 v1 = *(const float4*)&H[(size_t)c1 * HDIM + INOFF + f];
        float4 v2 = *(const float4*)&H[(size_t)c2 * HDIM + INOFF + f];
        float4 v3 = *(const float4*)&H[(size_t)c3 * HDIM + INOFF + f];
        acc.x = fmaf(w0, v0.x, fmaf(w1, v1.x, fmaf(w2, v2.x, fmaf(w3, v3.x, acc.x))));
        acc.y = fmaf(w0, v0.y, fmaf(w1, v1.y, fmaf(w2, v2.y, fmaf(w3, v3.y, acc.y))));
        acc.z = fmaf(w0, v0.z, fmaf(w1, v1.z, fmaf(w2, v2.z, fmaf(w3, v3.z, acc.z))));
        acc.w = fmaf(w0, v0.w, fmaf(w1, v1.w, fmaf(w2, v2.w, fmaf(w3, v3.w, acc.w))));
    }
    for (; j < e; j++) {
        int c0 = g_cols[j];
        float w0 = g_dinv[c0];
        float4 v0 = *(const float4*)&H[(size_t)c0 * HDIM + INOFF + f];
        acc.x = fmaf(w0, v0.x, acc.x);
        acc.y = fmaf(w0, v0.y, acc.y);
        acc.z = fmaf(w0, v0.z, acc.z);
        acc.w = fmaf(w0, v0.w, acc.w);
    }
    acc.x *= di; acc.y *= di; acc.z *= di; acc.w *= di;
    *(float4*)&g_H[(size_t)r * HDIM + OUTOFF + f] = acc;
}

// ---------------- GEMM2: logits = H @ Wc + b2  -> d_out ---------------------
// 64 rows x 40 cols per block, 320 threads (col = tid%40, 8 rows each).
__global__ void __launch_bounds__(320) k_gemm2(const float* __restrict__ bias,
                                               float* __restrict__ out) {
    __shared__ float Hs[64][36];   // pad to 36
    __shared__ float Wt[40][36];   // transposed: Wt[c][k]
    int bm = blockIdx.x * 64;
    int tid = threadIdx.x;
    int col = tid % 40;
    int rg = tid / 40;             // 0..7, handles rows rg*8 .. rg*8+7

    unsigned long long acc2[8];
#pragma unroll
    for (int i = 0; i < 8; i++) acc2[i] = 0ULL;

    for (int k0 = 0; k0 < HDIM; k0 += 32) {
        for (int i = tid; i < 32 * 40; i += 320) {
            Wt[i % 40][i / 40] = g_Wc[k0 * 40 + i];
        }
        for (int i = tid; i < 512; i += 320) {
            int r = i >> 3, kk = (i & 7) << 2;
            float4 v = make_float4(0.f, 0.f, 0.f, 0.f);
            if (bm + r < NN)
                v = *(const float4*)&g_H[(size_t)(bm + r) * HDIM + k0 + kk];
            Hs[r][kk + 0] = v.x; Hs[r][kk + 1] = v.y;
            Hs[r][kk + 2] = v.z; Hs[r][kk + 3] = v.w;
        }
        __syncthreads();
#pragma unroll
        for (int k = 0; k < 32; k += 4) {
            float4 w = *(const float4*)&Wt[col][k];
            unsigned long long wp0 = pk2(w.x, w.y);
            unsigned long long wp1 = pk2(w.z, w.w);
#pragma unroll
            for (int i = 0; i < 8; i++) {
                float4 h = *(const float4*)&Hs[rg * 8 + i][k];
                ffma2(acc2[i], pk2(h.x, h.y), wp0);
                ffma2(acc2[i], pk2(h.z, h.w), wp1);
            }
        }
        __syncthreads();
    }
    float b = bias[col];
#pragma unroll
    for (int i = 0; i < 8; i++) {
        int gr = bm + rg * 8 + i;
        if (gr < NN) {
            float lo, hi;
            upk2(acc2[i], lo, hi);
            out[(size_t)gr * NCLS + col] = lo + hi + b;
        }
    }
}

// ---------------- log_softmax in-place on [NN, 40], one warp per row --------
__global__ void k_logsoftmax(float* __restrict__ out) {
    int gt = blockIdx.x * blockDim.x + threadIdx.x;
    int r = gt >> 5;
    int lane = gt & 31;
    if (r >= NN) return;
    float* p = out + (size_t)r * NCLS;
    float v0 = p[lane];
    float v1 = (lane < 8) ? p[32 + lane] : -1e30f;
    float m = fmaxf(v0, v1);
#pragma unroll
    for (int o = 16; o; o >>= 1) m = fmaxf(m, __shfl_xor_sync(0xffffffffu, m, o));
    float s = expf(v0 - m) + ((lane < 8) ? expf(v1 - m) : 0.f);
#pragma unroll
    for (int o = 16; o; o >>= 1) s += __shfl_xor_sync(0xffffffffu, s, o);
    float lse = m + logf(s);
    p[lane] = v0 - lse;
    if (lane < 8) p[32 + lane] = v1 - lse;
}

// ---------------- entry -----------------------------------------------------
extern "C" void kernel_launch(void* const* d_in, const int* in_sizes, int n_in,
                              void* d_out, int out_size) {
    const float* x    = (const float*)d_in[0];
    const int*   erow = (const int*)d_in[1];
    const int*   ecol = (const int*)d_in[2];
    const float* W1   = (const float*)d_in[3];
    const float* b1   = (const float*)d_in[4];
    const float* W2   = (const float*)d_in[5];
    const float* b2   = (const float*)d_in[6];
    float* out = (float*)d_out;
    (void)in_sizes; (void)n_in; (void)out_size;

    // graph preprocessing
    k_zero_counts<<<(NN + 255) / 256, 256>>>();
    k_count<<<(NE + 255) / 256, 256>>>(erow, ecol);
    k_dinv<<<(NN + 255) / 256, 256>>>();
    k_scan<<<1, 1024>>>();
    k_scatter<<<(NE + 255) / 256, 256>>>(erow, ecol);
    k_wc<<<(HDIM * NCLS + 255) / 256, 256>>>(W2);

    // t = relu(x @ W1 + b1)  -> H[:,0:512]
    dim3 g1(DIMF / 128, (NN + 127) / 128);
    k_gemm1<<<g1, 256>>>(x, W1, b1);

    // s1 = spmm(t)   -> H[:,512:1024]
    k_spmm<0, 512><<<NN, 128>>>();
    // s2 = spmm(s1)  -> H[:,1024:1536]   (t2 = [s1, s2] handled in Wc fold)
    k_spmm<512, 1024><<<NN, 128>>>();

    // logits = H @ Wc + b2  (K = 1536, duplicated columns folded into Wc)
    k_gemm2<<<(NN + 63) / 64, 320>>>(b2, out);

    // log_softmax in-place
    k_logsoftmax<<<(NN * 32 + 255) / 256, 256>>>(out);
}

// round 7
// speedup vs baseline: 1.5522x; 1.1284x over previous
#include <cuda_runtime.h>
#include <cuda_fp16.h>

// Problem constants (fixed by the dataset)
#define NN    50000      // nodes
#define NE    1600000    // edges
#define FIN   512        // input features
#define DIMF  512        // hidden dim
#define NCLS  40         // classes
#define HDIM  1536       // H = [ t(512) | s1(512) | s2(512) ]
#define NBLK  49         // scan blocks: 49*1024 >= 50000

// ---------------- scratch (device globals: no cudaMalloc allowed) ----------
__device__ __align__(128) float  g_H[(size_t)NN * HDIM];    // ~307 MB
__device__ __align__(128) __half g_t16[(size_t)NN * DIMF];  // fp16 copy of t
__device__ __align__(128) __half g_s116[(size_t)NN * DIMF]; // fp16 copy of s1
__device__ __align__(128) float  g_Wc[HDIM * NCLS];         // combined W2
__device__ float g_dinv[NN];
__device__ int   g_degc[NN];
__device__ int   g_rcnt[NN];
__device__ int   g_rowptr[NN + 1];
__device__ int   g_cursor[NN];
__device__ int   g_cols[NE];
__device__ int   g_bsum[NBLK];
__device__ int   g_boff[NBLK];

// ---------------- f32x2 packed-FMA helpers ----------------------------------
__device__ __forceinline__ unsigned long long pk2(float x, float y) {
    unsigned long long r;
    asm("mov.b64 %0, {%1,%2};" : "=l"(r) : "f"(x), "f"(y));
    return r;
}
__device__ __forceinline__ unsigned long long dup2(float x) {
    unsigned long long r;
    asm("mov.b64 %0, {%1,%1};" : "=l"(r) : "f"(x));
    return r;
}
__device__ __forceinline__ void upk2(unsigned long long v, float& x, float& y) {
    asm("mov.b64 {%0,%1}, %2;" : "=f"(x), "=f"(y) : "l"(v));
}
__device__ __forceinline__ void ffma2(unsigned long long& d,
                                      unsigned long long a,
                                      unsigned long long b) {
    asm("fma.rn.f32x2 %0, %1, %2, %0;" : "+l"(d) : "l"(a), "l"(b));
}

// ---------------- graph preprocessing ---------------------------------------
__global__ void k_zero_counts() {
    int i = blockIdx.x * blockDim.x + threadIdx.x;
    if (i < NN) { g_degc[i] = 0; g_rcnt[i] = 0; g_cursor[i] = 0; }
}

__global__ void k_count(const int* __restrict__ erow, const int* __restrict__ ecol) {
    int e = blockIdx.x * blockDim.x + threadIdx.x;
    if (e < NE) {
        atomicAdd(&g_degc[ecol[e]], 1);
        atomicAdd(&g_rcnt[erow[e]], 1);
    }
}

// Phase 1: per-block inclusive scan of g_rcnt into g_rowptr[i+1] (local),
// block totals to g_bsum. Also computes dinv (independent work, fused).
__global__ void __launch_bounds__(1024) k_scan_part() {
    __shared__ int wsum[32];
    int lane = threadIdx.x & 31, wid = threadIdx.x >> 5;
    int i = blockIdx.x * 1024 + threadIdx.x;
    if (i < NN) g_dinv[i] = rsqrtf((float)(g_degc[i] + 1));  // +1 self loop
    int s = (i < NN) ? g_rcnt[i] : 0;
#pragma unroll
    for (int o = 1; o < 32; o <<= 1) {
        int t = __shfl_up_sync(0xffffffffu, s, o);
        if (lane >= o) s += t;
    }
    if (lane == 31) wsum[wid] = s;
    __syncthreads();
    if (wid == 0) {
        int ws = wsum[lane];
#pragma unroll
        for (int o = 1; o < 32; o <<= 1) {
            int t = __shfl_up_sync(0xffffffffu, ws, o);
            if (lane >= o) ws += t;
        }
        wsum[lane] = ws;
    }
    __syncthreads();
    s += (wid > 0 ? wsum[wid - 1] : 0);
    if (i < NN) g_rowptr[i + 1] = s;
    if (threadIdx.x == 1023) g_bsum[blockIdx.x] = s;
}

// Phase 2: exclusive scan of the NBLK block totals.
__global__ void k_scan_bsum() {
    __shared__ int sh[64];
    int t = threadIdx.x;
    int v = (t < NBLK) ? g_bsum[t] : 0;
    sh[t] = v;
    __syncthreads();
    for (int o = 1; o < 64; o <<= 1) {
        int u = (t >= o) ? sh[t - o] : 0;
        __syncthreads();
        sh[t] += u;
        __syncthreads();
    }
    if (t < NBLK) g_boff[t] = sh[t] - v;
}

// Phase 3: add block offsets.
__global__ void __launch_bounds__(1024) k_scan_add() {
    int i = blockIdx.x * 1024 + threadIdx.x;
    if (i < NN) g_rowptr[i + 1] += g_boff[blockIdx.x];
    if (i == 0) g_rowptr[0] = 0;
}

__global__ void k_scatter(const int* __restrict__ erow, const int* __restrict__ ecol) {
    int e = blockIdx.x * blockDim.x + threadIdx.x;
    if (e < NE) {
        int r = erow[e];
        int p = g_rowptr[r] + atomicAdd(&g_cursor[r], 1);
        g_cols[p] = ecol[e];
    }
}

// Combined classifier weight over [t(512) | s1(512) | s2(512)]:
//   Wc[0:512]     = W2[0:512]    + W2[512:1024]
//   Wc[512:1024]  = W2[1024:1536]+ W2[1536:2048]
//   Wc[1024:1536] = W2[2048:2560]
__global__ void k_wc(const float* __restrict__ W2) {
    int i = blockIdx.x * blockDim.x + threadIdx.x;
    const int S = 512 * NCLS;
    if (i < S)                      g_Wc[i] = W2[i] + W2[i + S];
    else if (i < 2 * S)             g_Wc[i] = W2[i + S] + W2[i + 2 * S];
    else if (i < HDIM * NCLS)       g_Wc[i] = W2[i + 2 * S];
}

// ---------------- GEMM1: t = relu(x @ W1 + b1) -> H[:, 0:512] + g_t16 -------
// 128x128 tile, BK=16, 8x8 per thread, 256 threads, packed f32x2 FMAs.
__global__ void __launch_bounds__(256) k_gemm1(const float* __restrict__ A,
                                               const float* __restrict__ B,
                                               const float* __restrict__ bias) {
    __shared__ float As[16][128];
    __shared__ float Bs[16][128];
    int bm = blockIdx.y * 128;
    int bn = blockIdx.x * 128;
    int tid = threadIdx.x;
    int tx = tid & 15, ty = tid >> 4;

    unsigned long long acc2[8][4];
#pragma unroll
    for (int i = 0; i < 8; i++)
#pragma unroll
        for (int j = 0; j < 4; j++) acc2[i][j] = 0ULL;

    for (int k0 = 0; k0 < FIN; k0 += 16) {
#pragma unroll
        for (int l = 0; l < 2; l++) {
            int i = tid + l * 256;
            int r = i >> 2, kk = (i & 3) * 4;
            float4 av = make_float4(0.f, 0.f, 0.f, 0.f);
            int gr = bm + r;
            if (gr < NN) av = *(const float4*)(A + (size_t)gr * FIN + k0 + kk);
            As[kk + 0][r] = av.x; As[kk + 1][r] = av.y;
            As[kk + 2][r] = av.z; As[kk + 3][r] = av.w;
            int br = i >> 5, bc = (i & 31) * 4;
            *(float4*)&Bs[br][bc] =
                *(const float4*)(B + (size_t)(k0 + br) * DIMF + bn + bc);
        }
        __syncthreads();
#pragma unroll
        for (int k = 0; k < 16; k++) {
            float4 a0 = *(const float4*)&As[k][ty * 8];
            float4 a1 = *(const float4*)&As[k][ty * 8 + 4];
            float4 b0 = *(const float4*)&Bs[k][tx * 8];
            float4 b1 = *(const float4*)&Bs[k][tx * 8 + 4];
            unsigned long long bp[4];
            bp[0] = pk2(b0.x, b0.y); bp[1] = pk2(b0.z, b0.w);
            bp[2] = pk2(b1.x, b1.y); bp[3] = pk2(b1.z, b1.w);
            unsigned long long ad[8];
            ad[0] = dup2(a0.x); ad[1] = dup2(a0.y);
            ad[2] = dup2(a0.z); ad[3] = dup2(a0.w);
            ad[4] = dup2(a1.x); ad[5] = dup2(a1.y);
            ad[6] = dup2(a1.z); ad[7] = dup2(a1.w);
#pragma unroll
            for (int i = 0; i < 8; i++)
#pragma unroll
                for (int jp = 0; jp < 4; jp++) ffma2(acc2[i][jp], ad[i], bp[jp]);
        }
        __syncthreads();
    }
#pragma unroll
    for (int i = 0; i < 8; i++) {
        int gr = bm + ty * 8 + i;
        if (gr < NN) {
#pragma unroll
            for (int jp = 0; jp < 4; jp += 2) {
                int gc = bn + tx * 8 + jp * 2;
                float4 o;
                upk2(acc2[i][jp + 0], o.x, o.y);
                upk2(acc2[i][jp + 1], o.z, o.w);
                o.x = fmaxf(o.x + bias[gc + 0], 0.f);
                o.y = fmaxf(o.y + bias[gc + 1], 0.f);
                o.z = fmaxf(o.z + bias[gc + 2], 0.f);
                o.w = fmaxf(o.w + bias[gc + 3], 0.f);
                *(float4*)&g_H[(size_t)gr * HDIM + gc] = o;
                __half2* p16 = (__half2*)(g_t16 + (size_t)gr * DIMF + gc);
                p16[0] = __floats2half2_rn(o.x, o.y);
                p16[1] = __floats2half2_rn(o.z, o.w);
            }
        }
    }
}

// ---------------- SpMM (fp16 gather, fp32 accumulate) ------------------------
// out[r] = dinv[r]*(sum_c dinv[c]*in16[c] + dinv[r]*in_fp32[r])
// PASS=1: in16=g_t16, self from H[:,0:512],  out -> H[:,512:1024] + g_s116
// PASS=2: in16=g_s116, self from H[:,512:1024], out -> H[:,1024:1536]
template <int PASS>
__global__ void __launch_bounds__(128) k_spmm16() {
    const __half* __restrict__ V = (PASS == 1) ? g_t16 : g_s116;
    const int INOFF  = (PASS == 1) ? 0   : 512;
    const int OUTOFF = (PASS == 1) ? 512 : 1024;
    int r = blockIdx.x;
    int f = threadIdx.x * 4;
    float di = g_dinv[r];

    float4 sv = *(const float4*)&g_H[(size_t)r * HDIM + INOFF + f];
    float4 acc;
    acc.x = di * sv.x; acc.y = di * sv.y; acc.z = di * sv.z; acc.w = di * sv.w;

    int s = g_rowptr[r], e = g_rowptr[r + 1];
    int j = s;
    for (; j + 3 < e; j += 4) {
        int c0 = g_cols[j], c1 = g_cols[j + 1];
        int c2 = g_cols[j + 2], c3 = g_cols[j + 3];
        float w0 = g_dinv[c0], w1 = g_dinv[c1];
        float w2 = g_dinv[c2], w3 = g_dinv[c3];
        uint2 p0 = *(const uint2*)(V + (size_t)c0 * DIMF + f);
        uint2 p1 = *(const uint2*)(V + (size_t)c1 * DIMF + f);
        uint2 p2 = *(const uint2*)(V + (size_t)c2 * DIMF + f);
        uint2 p3 = *(const uint2*)(V + (size_t)c3 * DIMF + f);
        float2 a0 = __half22float2(*(__half2*)&p0.x), b0 = __half22float2(*(__half2*)&p0.y);
        float2 a1 = __half22float2(*(__half2*)&p1.x), b1 = __half22float2(*(__half2*)&p1.y);
        float2 a2 = __half22float2(*(__half2*)&p2.x), b2 = __half22float2(*(__half2*)&p2.y);
        float2 a3 = __half22float2(*(__half2*)&p3.x), b3 = __half22float2(*(__half2*)&p3.y);
        acc.x = fmaf(w0, a0.x, fmaf(w1, a1.x, fmaf(w2, a2.x, fmaf(w3, a3.x, acc.x))));
        acc.y = fmaf(w0, a0.y, fmaf(w1, a1.y, fmaf(w2, a2.y, fmaf(w3, a3.y, acc.y))));
        acc.z = fmaf(w0, b0.x, fmaf(w1, b1.x, fmaf(w2, b2.x, fmaf(w3, b3.x, acc.z))));
        acc.w = fmaf(w0, b0.y, fmaf(w1, b1.y, fmaf(w2, b2.y, fmaf(w3, b3.y, acc.w))));
    }
    for (; j < e; j++) {
        int c0 = g_cols[j];
        float w0 = g_dinv[c0];
        uint2 p0 = *(const uint2*)(V + (size_t)c0 * DIMF + f);
        float2 a0 = __half22float2(*(__half2*)&p0.x), b0 = __half22float2(*(__half2*)&p0.y);
        acc.x = fmaf(w0, a0.x, acc.x);
        acc.y = fmaf(w0, a0.y, acc.y);
        acc.z = fmaf(w0, b0.x, acc.z);
        acc.w = fmaf(w0, b0.y, acc.w);
    }
    acc.x *= di; acc.y *= di; acc.z *= di; acc.w *= di;
    *(float4*)&g_H[(size_t)r * HDIM + OUTOFF + f] = acc;
    if (PASS == 1) {
        __half2* p16 = (__half2*)(g_s116 + (size_t)r * DIMF + f);
        p16[0] = __floats2half2_rn(acc.x, acc.y);
        p16[1] = __floats2half2_rn(acc.z, acc.w);
    }
}

// ---------------- GEMM2 + log_softmax fused: out = lsm(H @ Wc + b2) ---------
// 64 rows x 40 cols per block, 320 threads (col = tid%40, 8 rows each).
__global__ void __launch_bounds__(320) k_gemm2(const float* __restrict__ bias,
                                               float* __restrict__ out) {
    __shared__ float Hs[64][36];
    __shared__ float Wt[40][36];
    __shared__ float Ls[64][44];
    int bm = blockIdx.x * 64;
    int tid = threadIdx.x;
    int col = tid % 40;
    int rg = tid / 40;

    unsigned long long acc2[8];
#pragma unroll
    for (int i = 0; i < 8; i++) acc2[i] = 0ULL;

    for (int k0 = 0; k0 < HDIM; k0 += 32) {
        for (int i = tid; i < 32 * 40; i += 320) {
            Wt[i % 40][i / 40] = g_Wc[k0 * 40 + i];
        }
        for (int i = tid; i < 512; i += 320) {
            int r = i >> 3, kk = (i & 7) << 2;
            float4 v = make_float4(0.f, 0.f, 0.f, 0.f);
            if (bm + r < NN)
                v = *(const float4*)&g_H[(size_t)(bm + r) * HDIM + k0 + kk];
            Hs[r][kk + 0] = v.x; Hs[r][kk + 1] = v.y;
            Hs[r][kk + 2] = v.z; Hs[r][kk + 3] = v.w;
        }
        __syncthreads();
#pragma unroll
        for (int k = 0; k < 32; k += 4) {
            float4 w = *(const float4*)&Wt[col][k];
            unsigned long long wp0 = pk2(w.x, w.y);
            unsigned long long wp1 = pk2(w.z, w.w);
#pragma unroll
            for (int i = 0; i < 8; i++) {
                float4 h = *(const float4*)&Hs[rg * 8 + i][k];
                ffma2(acc2[i], pk2(h.x, h.y), wp0);
                ffma2(acc2[i], pk2(h.z, h.w), wp1);
            }
        }
        __syncthreads();
    }
    float b = bias[col];
#pragma unroll
    for (int i = 0; i < 8; i++) {
        float lo, hi;
        upk2(acc2[i], lo, hi);
        Ls[rg * 8 + i][col] = lo + hi + b;
    }
    __syncthreads();

    // fused log_softmax: 10 warps, each handles rows w, w+10, ...
    int w = tid >> 5, lane = tid & 31;
    for (int r = w; r < 64; r += 10) {
        int gr = bm + r;
        if (gr >= NN) continue;
        float v0 = Ls[r][lane];
        float v1 = (lane < 8) ? Ls[r][32 + lane] : -1e30f;
        float m = fmaxf(v0, v1);
#pragma unroll
        for (int o = 16; o; o >>= 1) m = fmaxf(m, __shfl_xor_sync(0xffffffffu, m, o));
        float sum = expf(v0 - m) + ((lane < 8) ? expf(v1 - m) : 0.f);
#pragma unroll
        for (int o = 16; o; o >>= 1) sum += __shfl_xor_sync(0xffffffffu, sum, o);
        float lse = m + logf(sum);
        float* p = out + (size_t)gr * NCLS;
        p[lane] = v0 - lse;
        if (lane < 8) p[32 + lane] = v1 - lse;
    }
}

// ---------------- entry -----------------------------------------------------
extern "C" void kernel_launch(void* const* d_in, const int* in_sizes, int n_in,
                              void* d_out, int out_size) {
    const float* x    = (const float*)d_in[0];
    const int*   erow = (const int*)d_in[1];
    const int*   ecol = (const int*)d_in[2];
    const float* W1   = (const float*)d_in[3];
    const float* b1   = (const float*)d_in[4];
    const float* W2   = (const float*)d_in[5];
    const float* b2   = (const float*)d_in[6];
    float* out = (float*)d_out;
    (void)in_sizes; (void)n_in; (void)out_size;

    // 1-3: preprocessing start (dinv fused into scan_part)
    k_zero_counts<<<(NN + 255) / 256, 256>>>();
    k_count<<<(NE + 255) / 256, 256>>>(erow, ecol);
    k_scan_part<<<NBLK, 1024>>>();

    // 4: GEMM1 (independent of graph) — placed 4th so ncu captures it
    dim3 g1(DIMF / 128, (NN + 127) / 128);
    k_gemm1<<<g1, 256>>>(x, W1, b1);

    // 5-8: finish preprocessing
    k_scan_bsum<<<1, 64>>>();
    k_scan_add<<<NBLK, 1024>>>();
    k_scatter<<<(NE + 255) / 256, 256>>>(erow, ecol);
    k_wc<<<(HDIM * NCLS + 255) / 256, 256>>>(W2);

    // 9-10: SpMM passes (fp16 gather)
    k_spmm16<1><<<NN, 128>>>();
    k_spmm16<2><<<NN, 128>>>();

    // 11: GEMM2 + log_softmax fused
    k_gemm2<<<(NN + 63) / 64, 320>>>(b2, out);
}

// round 8
// speedup vs baseline: 2.3105x; 1.4885x over previous
#include <cuda_runtime.h>
#include <cuda_fp16.h>
#include <cstdint>

// Problem constants (fixed by the dataset)
#define NN    50000      // nodes
#define NE    1600000    // edges
#define FIN   512        // input features
#define DIMF  512        // hidden dim
#define NCLS  40         // classes
#define HDIM  1536       // H = [ t(512) | s1(512) | s2(512) ]
#define NBLK  49         // scan blocks: 49*1024 >= 50000

// ---------------- scratch (device globals: no cudaMalloc allowed) ----------
__device__ __align__(128) float  g_H[(size_t)NN * HDIM];    // ~307 MB
__device__ __align__(128) __half g_x16[(size_t)NN * FIN];   // fp16 copy of x
__device__ __align__(128) __half g_w16[FIN * DIMF];         // fp16 copy of W1
__device__ __align__(128) __half g_t16[(size_t)NN * DIMF];  // fp16 copy of t
__device__ __align__(128) __half g_s116[(size_t)NN * DIMF]; // fp16 copy of s1
__device__ __align__(128) float  g_Wc[HDIM * NCLS];         // combined W2
__device__ float g_dinv[NN];
__device__ int   g_degc[NN];
__device__ int   g_rcnt[NN];
__device__ int   g_rowptr[NN + 1];
__device__ int   g_cursor[NN];
__device__ int   g_cols[NE];
__device__ int   g_bsum[NBLK];
__device__ int   g_boff[NBLK];

// ---------------- f32x2 packed-FMA helpers (GEMM2) ---------------------------
__device__ __forceinline__ unsigned long long pk2(float x, float y) {
    unsigned long long r;
    asm("mov.b64 %0, {%1,%2};" : "=l"(r) : "f"(x), "f"(y));
    return r;
}
__device__ __forceinline__ void upk2(unsigned long long v, float& x, float& y) {
    asm("mov.b64 {%0,%1}, %2;" : "=f"(x), "=f"(y) : "l"(v));
}
__device__ __forceinline__ void ffma2(unsigned long long& d,
                                      unsigned long long a,
                                      unsigned long long b) {
    asm("fma.rn.f32x2 %0, %1, %2, %0;" : "+l"(d) : "l"(a), "l"(b));
}

// ---------------- tensor-core helpers ----------------------------------------
__device__ __forceinline__ uint32_t smem_u32(const void* p) {
    return (uint32_t)__cvta_generic_to_shared(p);
}
__device__ __forceinline__ void ldsm_x4(uint32_t& r0, uint32_t& r1,
                                        uint32_t& r2, uint32_t& r3, uint32_t a) {
    asm volatile("ldmatrix.sync.aligned.m8n8.x4.shared.b16 {%0,%1,%2,%3}, [%4];"
                 : "=r"(r0), "=r"(r1), "=r"(r2), "=r"(r3) : "r"(a));
}
__device__ __forceinline__ void ldsm_x2t(uint32_t& r0, uint32_t& r1, uint32_t a) {
    asm volatile("ldmatrix.sync.aligned.m8n8.x2.trans.shared.b16 {%0,%1}, [%2];"
                 : "=r"(r0), "=r"(r1) : "r"(a));
}
__device__ __forceinline__ void mma16816(float* c, const uint32_t* a, const uint32_t* b) {
    asm volatile("mma.sync.aligned.m16n8k16.row.col.f32.f16.f16.f32 "
                 "{%0,%1,%2,%3}, {%4,%5,%6,%7}, {%8,%9}, {%0,%1,%2,%3};"
                 : "+f"(c[0]), "+f"(c[1]), "+f"(c[2]), "+f"(c[3])
                 : "r"(a[0]), "r"(a[1]), "r"(a[2]), "r"(a[3]), "r"(b[0]), "r"(b[1]));
}
__device__ __forceinline__ void cp16(uint32_t dst, const void* src, int src_bytes) {
    asm volatile("cp.async.cg.shared.global [%0], [%1], 16, %2;"
                 :: "r"(dst), "l"(src), "r"(src_bytes));
}

// ---------------- fp16 cast of x and W1 --------------------------------------
__global__ void k_xcast(const float* __restrict__ x, const float* __restrict__ W1) {
    size_t i = (size_t)blockIdx.x * blockDim.x + threadIdx.x;   // float4 index
    const size_t nx4 = (size_t)NN * FIN / 4;
    const size_t nw4 = (size_t)FIN * DIMF / 4;
    if (i < nx4) {
        float4 v = ((const float4*)x)[i];
        __half2 h0 = __floats2half2_rn(v.x, v.y);
        __half2 h1 = __floats2half2_rn(v.z, v.w);
        *(uint2*)(g_x16 + i * 4) = make_uint2(*(uint32_t*)&h0, *(uint32_t*)&h1);
    } else if (i < nx4 + nw4) {
        size_t j = i - nx4;
        float4 v = ((const float4*)W1)[j];
        __half2 h0 = __floats2half2_rn(v.x, v.y);
        __half2 h1 = __floats2half2_rn(v.z, v.w);
        *(uint2*)(g_w16 + j * 4) = make_uint2(*(uint32_t*)&h0, *(uint32_t*)&h1);
    }
}

// ---------------- graph preprocessing ---------------------------------------
__global__ void k_zero_counts() {
    int i = blockIdx.x * blockDim.x + threadIdx.x;
    if (i < NN) { g_degc[i] = 0; g_rcnt[i] = 0; g_cursor[i] = 0; }
}

__global__ void k_count(const int* __restrict__ erow, const int* __restrict__ ecol) {
    int e = blockIdx.x * blockDim.x + threadIdx.x;
    if (e < NE) {
        atomicAdd(&g_degc[ecol[e]], 1);
        atomicAdd(&g_rcnt[erow[e]], 1);
    }
}

__global__ void __launch_bounds__(1024) k_scan_part() {
    __shared__ int wsum[32];
    int lane = threadIdx.x & 31, wid = threadIdx.x >> 5;
    int i = blockIdx.x * 1024 + threadIdx.x;
    if (i < NN) g_dinv[i] = rsqrtf((float)(g_degc[i] + 1));  // +1 self loop
    int s = (i < NN) ? g_rcnt[i] : 0;
#pragma unroll
    for (int o = 1; o < 32; o <<= 1) {
        int t = __shfl_up_sync(0xffffffffu, s, o);
        if (lane >= o) s += t;
    }
    if (lane == 31) wsum[wid] = s;
    __syncthreads();
    if (wid == 0) {
        int ws = wsum[lane];
#pragma unroll
        for (int o = 1; o < 32; o <<= 1) {
            int t = __shfl_up_sync(0xffffffffu, ws, o);
            if (lane >= o) ws += t;
        }
        wsum[lane] = ws;
    }
    __syncthreads();
    s += (wid > 0 ? wsum[wid - 1] : 0);
    if (i < NN) g_rowptr[i + 1] = s;
    if (threadIdx.x == 1023) g_bsum[blockIdx.x] = s;
}

__global__ void k_scan_bsum() {
    __shared__ int sh[64];
    int t = threadIdx.x;
    int v = (t < NBLK) ? g_bsum[t] : 0;
    sh[t] = v;
    __syncthreads();
    for (int o = 1; o < 64; o <<= 1) {
        int u = (t >= o) ? sh[t - o] : 0;
        __syncthreads();
        sh[t] += u;
        __syncthreads();
    }
    if (t < NBLK) g_boff[t] = sh[t] - v;
}

__global__ void __launch_bounds__(1024) k_scan_add() {
    int i = blockIdx.x * 1024 + threadIdx.x;
    if (i < NN) g_rowptr[i + 1] += g_boff[blockIdx.x];
    if (i == 0) g_rowptr[0] = 0;
}

__global__ void k_scatter(const int* __restrict__ erow, const int* __restrict__ ecol) {
    int e = blockIdx.x * blockDim.x + threadIdx.x;
    if (e < NE) {
        int r = erow[e];
        int p = g_rowptr[r] + atomicAdd(&g_cursor[r], 1);
        g_cols[p] = ecol[e];
    }
}

// Combined classifier weight over [t(512) | s1(512) | s2(512)]
__global__ void k_wc(const float* __restrict__ W2) {
    int i = blockIdx.x * blockDim.x + threadIdx.x;
    const int S = 512 * NCLS;
    if (i < S)                      g_Wc[i] = W2[i] + W2[i + S];
    else if (i < 2 * S)             g_Wc[i] = W2[i + S] + W2[i + 2 * S];
    else if (i < HDIM * NCLS)       g_Wc[i] = W2[i + 2 * S];
}

// ---------------- GEMM1 (tensor cores): t = relu(x16 @ w16 + b1) ------------
// 128x128 tile, BK=32, 8 warps (2x4), warp tile 64x32, mma.m16n8k16 fp32 acc.
// A/B tiles staged fp16 via cp.async, double buffered.
__global__ void __launch_bounds__(256) k_gemm1(const float* __restrict__ bias) {
    __shared__ __align__(16) __half As[2][128][40];   // pad 40: row stride 80 B
    __shared__ __align__(16) __half Bs[2][32][136];   // pad 136: row stride 272 B

    int bm = blockIdx.y * 128;
    int bn = blockIdx.x * 128;
    int tid = threadIdx.x;
    int wid = tid >> 5, ln = tid & 31;
    int wmb = (wid & 1) * 64;
    int wnb = (wid >> 1) * 32;

    float acc[4][4][4];
#pragma unroll
    for (int mt = 0; mt < 4; mt++)
#pragma unroll
        for (int nt = 0; nt < 4; nt++)
#pragma unroll
            for (int q = 0; q < 4; q++) acc[mt][nt][q] = 0.f;

    // ---- cp.async tile loader ----
    auto cp_load = [&](int buf, int k0) {
#pragma unroll
        for (int l = 0; l < 2; l++) {
            int ch = tid + l * 256;                 // 0..511
            int ar = ch >> 2, ak = (ch & 3) << 3;   // 4 chunks/row (32 halves)
            int gr = bm + ar;
            const __half* src = g_x16 + ((gr < NN) ? ((size_t)gr * FIN + k0 + ak) : 0);
            cp16(smem_u32(&As[buf][ar][ak]), src, (gr < NN) ? 16 : 0);
        }
#pragma unroll
        for (int l = 0; l < 2; l++) {
            int ch = tid + l * 256;                 // 0..511
            int br = ch >> 4, bc = (ch & 15) << 3;  // 16 chunks/row (128 halves)
            cp16(smem_u32(&Bs[buf][br][bc]),
                 g_w16 + (size_t)(k0 + br) * DIMF + bn + bc, 16);
        }
    };

    int arow = ln & 15;
    int acol8 = (ln >> 4) << 3;

    cp_load(0, 0);
    asm volatile("cp.async.commit_group;");

    for (int kt = 0; kt < 16; kt++) {
        int cur = kt & 1;
        if (kt + 1 < 16) {
            cp_load(cur ^ 1, (kt + 1) * 32);
            asm volatile("cp.async.commit_group;");
            asm volatile("cp.async.wait_group 1;");
        } else {
            asm volatile("cp.async.wait_group 0;");
        }
        __syncthreads();
#pragma unroll
        for (int ks = 0; ks < 2; ks++) {
            uint32_t a[4][4], b[4][2];
#pragma unroll
            for (int mt = 0; mt < 4; mt++)
                ldsm_x4(a[mt][0], a[mt][1], a[mt][2], a[mt][3],
                        smem_u32(&As[cur][wmb + mt * 16 + arow][ks * 16 + acol8]));
#pragma unroll
            for (int nt = 0; nt < 4; nt++)
                ldsm_x2t(b[nt][0], b[nt][1],
                         smem_u32(&Bs[cur][ks * 16 + arow][wnb + nt * 8]));
#pragma unroll
            for (int mt = 0; mt < 4; mt++)
#pragma unroll
                for (int nt = 0; nt < 4; nt++)
                    mma16816(acc[mt][nt], a[mt], b[nt]);
        }
        __syncthreads();
    }

    // ---- epilogue: bias + relu -> g_H fp32 and g_t16 fp16 ----
    int gq = ln >> 2, tq = ln & 3;
#pragma unroll
    for (int mt = 0; mt < 4; mt++) {
        int r0 = bm + wmb + mt * 16 + gq;
        int r1 = r0 + 8;
#pragma unroll
        for (int nt = 0; nt < 4; nt++) {
            int c = bn + wnb + nt * 8 + tq * 2;
            float bx = bias[c], by = bias[c + 1];
            float* ac = acc[mt][nt];
            if (r0 < NN) {
                float ox = fmaxf(ac[0] + bx, 0.f), oy = fmaxf(ac[1] + by, 0.f);
                *(float2*)&g_H[(size_t)r0 * HDIM + c] = make_float2(ox, oy);
                *(__half2*)(g_t16 + (size_t)r0 * DIMF + c) = __floats2half2_rn(ox, oy);
            }
            if (r1 < NN) {
                float ox = fmaxf(ac[2] + bx, 0.f), oy = fmaxf(ac[3] + by, 0.f);
                *(float2*)&g_H[(size_t)r1 * HDIM + c] = make_float2(ox, oy);
                *(__half2*)(g_t16 + (size_t)r1 * DIMF + c) = __floats2half2_rn(ox, oy);
            }
        }
    }
}

// ---------------- SpMM (fp16 gather, fp32 accumulate) ------------------------
template <int PASS>
__global__ void __launch_bounds__(128) k_spmm16() {
    const __half* __restrict__ V = (PASS == 1) ? g_t16 : g_s116;
    const int INOFF  = (PASS == 1) ? 0   : 512;
    const int OUTOFF = (PASS == 1) ? 512 : 1024;
    int r = blockIdx.x;
    int f = threadIdx.x * 4;
    float di = g_dinv[r];

    float4 sv = *(const float4*)&g_H[(size_t)r * HDIM + INOFF + f];
    float4 acc;
    acc.x = di * sv.x; acc.y = di * sv.y; acc.z = di * sv.z; acc.w = di * sv.w;

    int s = g_rowptr[r], e = g_rowptr[r + 1];
    int j = s;
    for (; j + 3 < e; j += 4) {
        int c0 = g_cols[j], c1 = g_cols[j + 1];
        int c2 = g_cols[j + 2], c3 = g_cols[j + 3];
        float w0 = g_dinv[c0], w1 = g_dinv[c1];
        float w2 = g_dinv[c2], w3 = g_dinv[c3];
        uint2 p0 = *(const uint2*)(V + (size_t)c0 * DIMF + f);
        uint2 p1 = *(const uint2*)(V + (size_t)c1 * DIMF + f);
        uint2 p2 = *(const uint2*)(V + (size_t)c2 * DIMF + f);
        uint2 p3 = *(const uint2*)(V + (size_t)c3 * DIMF + f);
        float2 a0 = __half22float2(*(__half2*)&p0.x), b0 = __half22float2(*(__half2*)&p0.y);
        float2 a1 = __half22float2(*(__half2*)&p1.x), b1 = __half22float2(*(__half2*)&p1.y);
        float2 a2 = __half22float2(*(__half2*)&p2.x), b2 = __half22float2(*(__half2*)&p2.y);
        float2 a3 = __half22float2(*(__half2*)&p3.x), b3 = __half22float2(*(__half2*)&p3.y);
        acc.x = fmaf(w0, a0.x, fmaf(w1, a1.x, fmaf(w2, a2.x, fmaf(w3, a3.x, acc.x))));
        acc.y = fmaf(w0, a0.y, fmaf(w1, a1.y, fmaf(w2, a2.y, fmaf(w3, a3.y, acc.y))));
        acc.z = fmaf(w0, b0.x, fmaf(w1, b1.x, fmaf(w2, b2.x, fmaf(w3, b3.x, acc.z))));
        acc.w = fmaf(w0, b0.y, fmaf(w1, b1.y, fmaf(w2, b2.y, fmaf(w3, b3.y, acc.w))));
    }
    for (; j < e; j++) {
        int c0 = g_cols[j];
        float w0 = g_dinv[c0];
        uint2 p0 = *(const uint2*)(V + (size_t)c0 * DIMF + f);
        float2 a0 = __half22float2(*(__half2*)&p0.x), b0 = __half22float2(*(__half2*)&p0.y);
        acc.x = fmaf(w0, a0.x, acc.x);
        acc.y = fmaf(w0, a0.y, acc.y);
        acc.z = fmaf(w0, b0.x, acc.z);
        acc.w = fmaf(w0, b0.y, acc.w);
    }
    acc.x *= di; acc.y *= di; acc.z *= di; acc.w *= di;
    *(float4*)&g_H[(size_t)r * HDIM + OUTOFF + f] = acc;
    if (PASS == 1) {
        __half2* p16 = (__half2*)(g_s116 + (size_t)r * DIMF + f);
        p16[0] = __floats2half2_rn(acc.x, acc.y);
        p16[1] = __floats2half2_rn(acc.z, acc.w);
    }
}

// ---------------- GEMM2 + log_softmax fused: out = lsm(H @ Wc + b2) ---------
__global__ void __launch_bounds__(320) k_gemm2(const float* __restrict__ bias,
                                               float* __restrict__ out) {
    __shared__ float Hs[64][36];
    __shared__ float Wt[40][36];
    __shared__ float Ls[64][44];
    int bm = blockIdx.x * 64;
    int tid = threadIdx.x;
    int col = tid % 40;
    int rg = tid / 40;

    unsigned long long acc2[8];
#pragma unroll
    for (int i = 0; i < 8; i++) acc2[i] = 0ULL;

    for (int k0 = 0; k0 < HDIM; k0 += 32) {
        for (int i = tid; i < 32 * 40; i += 320) {
            Wt[i % 40][i / 40] = g_Wc[k0 * 40 + i];
        }
        for (int i = tid; i < 512; i += 320) {
            int r = i >> 3, kk = (i & 7) << 2;
            float4 v = make_float4(0.f, 0.f, 0.f, 0.f);
            if (bm + r < NN)
                v = *(const float4*)&g_H[(size_t)(bm + r) * HDIM + k0 + kk];
            Hs[r][kk + 0] = v.x; Hs[r][kk + 1] = v.y;
            Hs[r][kk + 2] = v.z; Hs[r][kk + 3] = v.w;
        }
        __syncthreads();
#pragma unroll
        for (int k = 0; k < 32; k += 4) {
            float4 w = *(const float4*)&Wt[col][k];
            unsigned long long wp0 = pk2(w.x, w.y);
            unsigned long long wp1 = pk2(w.z, w.w);
#pragma unroll
            for (int i = 0; i < 8; i++) {
                float4 h = *(const float4*)&Hs[rg * 8 + i][k];
                ffma2(acc2[i], pk2(h.x, h.y), wp0);
                ffma2(acc2[i], pk2(h.z, h.w), wp1);
            }
        }
        __syncthreads();
    }
    float b = bias[col];
#pragma unroll
    for (int i = 0; i < 8; i++) {
        float lo, hi;
        upk2(acc2[i], lo, hi);
        Ls[rg * 8 + i][col] = lo + hi + b;
    }
    __syncthreads();

    int w = tid >> 5, lane = tid & 31;
    for (int r = w; r < 64; r += 10) {
        int gr = bm + r;
        if (gr >= NN) continue;
        float v0 = Ls[r][lane];
        float v1 = (lane < 8) ? Ls[r][32 + lane] : -1e30f;
        float m = fmaxf(v0, v1);
#pragma unroll
        for (int o = 16; o; o >>= 1) m = fmaxf(m, __shfl_xor_sync(0xffffffffu, m, o));
        float sum = expf(v0 - m) + ((lane < 8) ? expf(v1 - m) : 0.f);
#pragma unroll
        for (int o = 16; o; o >>= 1) sum += __shfl_xor_sync(0xffffffffu, sum, o);
        float lse = m + logf(sum);
        float* p = out + (size_t)gr * NCLS;
        p[lane] = v0 - lse;
        if (lane < 8) p[32 + lane] = v1 - lse;
    }
}

// ---------------- entry -----------------------------------------------------
extern "C" void kernel_launch(void* const* d_in, const int* in_sizes, int n_in,
                              void* d_out, int out_size) {
    const float* x    = (const float*)d_in[0];
    const int*   erow = (const int*)d_in[1];
    const int*   ecol = (const int*)d_in[2];
    const float* W1   = (const float*)d_in[3];
    const float* b1   = (const float*)d_in[4];
    const float* W2   = (const float*)d_in[5];
    const float* b2   = (const float*)d_in[6];
    float* out = (float*)d_out;
    (void)in_sizes; (void)n_in; (void)out_size;

    // 1: fp16 casts of x and W1
    const size_t ncast4 = (size_t)NN * FIN / 4 + (size_t)FIN * DIMF / 4;
    k_xcast<<<(unsigned)((ncast4 + 255) / 256), 256>>>(x, W1);

    // 2-3: preprocessing start
    k_zero_counts<<<(NN + 255) / 256, 256>>>();
    k_count<<<(NE + 255) / 256, 256>>>(erow, ecol);

    // 4: GEMM1 (tensor cores) — slot 4 so ncu captures it
    dim3 g1(DIMF / 128, (NN + 127) / 128);
    k_gemm1<<<g1, 256>>>(b1);

    // 5-9: finish preprocessing
    k_scan_part<<<NBLK, 1024>>>();
    k_scan_bsum<<<1, 64>>>();
    k_scan_add<<<NBLK, 1024>>>();
    k_scatter<<<(NE + 255) / 256, 256>>>(erow, ecol);
    k_wc<<<(HDIM * NCLS + 255) / 256, 256>>>(W2);

    // 10-11: SpMM passes (fp16 gather)
    k_spmm16<1><<<NN, 128>>>();
    k_spmm16<2><<<NN, 128>>>();

    // 12: GEMM2 + log_softmax fused
    k_gemm2<<<(NN + 63) / 64, 320>>>(b2, out);
}

// round 9
// speedup vs baseline: 4.7166x; 2.0414x over previous
#include <cuda_runtime.h>
#include <cuda_fp16.h>
#include <cstdint>

// Problem constants (fixed by the dataset)
#define NN    50000      // nodes
#define NE    1600000    // edges
#define FIN   512        // input features
#define DIMF  512        // hidden dim
#define NCLS  40         // classes
#define HDIM  1536       // F16 = [ t(512) | s1(512) | s2(512) ]
#define NBLK  49         // scan blocks: 49*1024 >= 50000

// ---------------- scratch (device globals: no cudaMalloc allowed) ----------
__device__ __align__(128) __half g_F16[(size_t)NN * HDIM];  // ~150 MB features
__device__ __align__(128) __half g_x16[(size_t)NN * FIN];   // fp16 copy of x
__device__ __align__(128) __half g_w16[FIN * DIMF];         // fp16 copy of W1
__device__ __align__(128) __half g_Wc16[HDIM * NCLS];       // fp16 combined W2
__device__ float g_dinv[NN];
__device__ int   g_degc[NN];
__device__ int   g_rcnt[NN];
__device__ int   g_rowptr[NN + 1];
__device__ int   g_cursor[NN];
__device__ int   g_cols[NE];
__device__ int   g_bsum[NBLK];
__device__ int   g_boff[NBLK];

// ---------------- tensor-core helpers ----------------------------------------
__device__ __forceinline__ uint32_t smem_u32(const void* p) {
    return (uint32_t)__cvta_generic_to_shared(p);
}
__device__ __forceinline__ void ldsm_x4(uint32_t& r0, uint32_t& r1,
                                        uint32_t& r2, uint32_t& r3, uint32_t a) {
    asm volatile("ldmatrix.sync.aligned.m8n8.x4.shared.b16 {%0,%1,%2,%3}, [%4];"
                 : "=r"(r0), "=r"(r1), "=r"(r2), "=r"(r3) : "r"(a));
}
__device__ __forceinline__ void ldsm_x2t(uint32_t& r0, uint32_t& r1, uint32_t a) {
    asm volatile("ldmatrix.sync.aligned.m8n8.x2.trans.shared.b16 {%0,%1}, [%2];"
                 : "=r"(r0), "=r"(r1) : "r"(a));
}
__device__ __forceinline__ void mma16816(float* c, const uint32_t* a, const uint32_t* b) {
    asm volatile("mma.sync.aligned.m16n8k16.row.col.f32.f16.f16.f32 "
                 "{%0,%1,%2,%3}, {%4,%5,%6,%7}, {%8,%9}, {%0,%1,%2,%3};"
                 : "+f"(c[0]), "+f"(c[1]), "+f"(c[2]), "+f"(c[3])
                 : "r"(a[0]), "r"(a[1]), "r"(a[2]), "r"(a[3]), "r"(b[0]), "r"(b[1]));
}
__device__ __forceinline__ void cp16(uint32_t dst, const void* src, int src_bytes) {
    asm volatile("cp.async.cg.shared.global [%0], [%1], 16, %2;"
                 :: "r"(dst), "l"(src), "r"(src_bytes));
}

// ---------------- fp16 cast of x and W1 --------------------------------------
__global__ void k_xcast(const float* __restrict__ x, const float* __restrict__ W1) {
    size_t i = (size_t)blockIdx.x * blockDim.x + threadIdx.x;   // float4 index
    const size_t nx4 = (size_t)NN * FIN / 4;
    const size_t nw4 = (size_t)FIN * DIMF / 4;
    if (i < nx4) {
        float4 v = ((const float4*)x)[i];
        __half2 h0 = __floats2half2_rn(v.x, v.y);
        __half2 h1 = __floats2half2_rn(v.z, v.w);
        *(uint2*)(g_x16 + i * 4) = make_uint2(*(uint32_t*)&h0, *(uint32_t*)&h1);
    } else if (i < nx4 + nw4) {
        size_t j = i - nx4;
        float4 v = ((const float4*)W1)[j];
        __half2 h0 = __floats2half2_rn(v.x, v.y);
        __half2 h1 = __floats2half2_rn(v.z, v.w);
        *(uint2*)(g_w16 + j * 4) = make_uint2(*(uint32_t*)&h0, *(uint32_t*)&h1);
    }
}

// ---------------- graph preprocessing ---------------------------------------
__global__ void k_zero_counts() {
    int i = blockIdx.x * blockDim.x + threadIdx.x;
    if (i < NN) { g_degc[i] = 0; g_rcnt[i] = 0; g_cursor[i] = 0; }
}

__global__ void k_count(const int* __restrict__ erow, const int* __restrict__ ecol) {
    int e = blockIdx.x * blockDim.x + threadIdx.x;
    if (e < NE) {
        atomicAdd(&g_degc[ecol[e]], 1);
        atomicAdd(&g_rcnt[erow[e]], 1);
    }
}

__global__ void __launch_bounds__(1024) k_scan_part() {
    __shared__ int wsum[32];
    int lane = threadIdx.x & 31, wid = threadIdx.x >> 5;
    int i = blockIdx.x * 1024 + threadIdx.x;
    if (i < NN) g_dinv[i] = rsqrtf((float)(g_degc[i] + 1));  // +1 self loop
    int s = (i < NN) ? g_rcnt[i] : 0;
#pragma unroll
    for (int o = 1; o < 32; o <<= 1) {
        int t = __shfl_up_sync(0xffffffffu, s, o);
        if (lane >= o) s += t;
    }
    if (lane == 31) wsum[wid] = s;
    __syncthreads();
    if (wid == 0) {
        int ws = wsum[lane];
#pragma unroll
        for (int o = 1; o < 32; o <<= 1) {
            int t = __shfl_up_sync(0xffffffffu, ws, o);
            if (lane >= o) ws += t;
        }
        wsum[lane] = ws;
    }
    __syncthreads();
    s += (wid > 0 ? wsum[wid - 1] : 0);
    if (i < NN) g_rowptr[i + 1] = s;
    if (threadIdx.x == 1023) g_bsum[blockIdx.x] = s;
}

__global__ void k_scan_bsum() {
    __shared__ int sh[64];
    int t = threadIdx.x;
    int v = (t < NBLK) ? g_bsum[t] : 0;
    sh[t] = v;
    __syncthreads();
    for (int o = 1; o < 64; o <<= 1) {
        int u = (t >= o) ? sh[t - o] : 0;
        __syncthreads();
        sh[t] += u;
        __syncthreads();
    }
    if (t < NBLK) g_boff[t] = sh[t] - v;
}

__global__ void __launch_bounds__(1024) k_scan_add() {
    int i = blockIdx.x * 1024 + threadIdx.x;
    if (i < NN) g_rowptr[i + 1] += g_boff[blockIdx.x];
    if (i == 0) g_rowptr[0] = 0;
}

__global__ void k_scatter(const int* __restrict__ erow, const int* __restrict__ ecol) {
    int e = blockIdx.x * blockDim.x + threadIdx.x;
    if (e < NE) {
        int r = erow[e];
        int p = g_rowptr[r] + atomicAdd(&g_cursor[r], 1);
        g_cols[p] = ecol[e];
    }
}

// Combined classifier weight over [t | s1 | s2], cast to fp16:
//   Wc[0:512]     = W2[0:512]    + W2[512:1024]
//   Wc[512:1024]  = W2[1024:1536]+ W2[1536:2048]
//   Wc[1024:1536] = W2[2048:2560]
__global__ void k_wc16(const float* __restrict__ W2) {
    int i = blockIdx.x * blockDim.x + threadIdx.x;
    if (i >= HDIM * NCLS) return;
    const int S = 512 * NCLS;
    float v;
    if (i < S)          v = W2[i] + W2[i + S];
    else if (i < 2 * S) v = W2[i + S] + W2[i + 2 * S];
    else                v = W2[i + 2 * S];
    g_Wc16[i] = __float2half_rn(v);
}

// ---------------- GEMM1 (tensor cores): t = relu(x16 @ w16 + b1) ------------
// 128x128 tile, BK=32, 8 warps (2x4), warp tile 64x32, mma.m16n8k16 fp32 acc.
__global__ void __launch_bounds__(256) k_gemm1(const float* __restrict__ bias) {
    __shared__ __align__(16) __half As[2][128][40];   // pad 40: row stride 80 B
    __shared__ __align__(16) __half Bs[2][32][136];   // pad 136: row stride 272 B

    int bm = blockIdx.y * 128;
    int bn = blockIdx.x * 128;
    int tid = threadIdx.x;
    int wid = tid >> 5, ln = tid & 31;
    int wmb = (wid & 1) * 64;
    int wnb = (wid >> 1) * 32;

    float acc[4][4][4];
#pragma unroll
    for (int mt = 0; mt < 4; mt++)
#pragma unroll
        for (int nt = 0; nt < 4; nt++)
#pragma unroll
            for (int q = 0; q < 4; q++) acc[mt][nt][q] = 0.f;

    auto cp_load = [&](int buf, int k0) {
#pragma unroll
        for (int l = 0; l < 2; l++) {
            int ch = tid + l * 256;
            int ar = ch >> 2, ak = (ch & 3) << 3;
            int gr = bm + ar;
            const __half* src = g_x16 + ((gr < NN) ? ((size_t)gr * FIN + k0 + ak) : 0);
            cp16(smem_u32(&As[buf][ar][ak]), src, (gr < NN) ? 16 : 0);
        }
#pragma unroll
        for (int l = 0; l < 2; l++) {
            int ch = tid + l * 256;
            int br = ch >> 4, bc = (ch & 15) << 3;
            cp16(smem_u32(&Bs[buf][br][bc]),
                 g_w16 + (size_t)(k0 + br) * DIMF + bn + bc, 16);
        }
    };

    int arow = ln & 15;
    int acol8 = (ln >> 4) << 3;

    cp_load(0, 0);
    asm volatile("cp.async.commit_group;");

    for (int kt = 0; kt < 16; kt++) {
        int cur = kt & 1;
        if (kt + 1 < 16) {
            cp_load(cur ^ 1, (kt + 1) * 32);
            asm volatile("cp.async.commit_group;");
            asm volatile("cp.async.wait_group 1;");
        } else {
            asm volatile("cp.async.wait_group 0;");
        }
        __syncthreads();
#pragma unroll
        for (int ks = 0; ks < 2; ks++) {
            uint32_t a[4][4], b[4][2];
#pragma unroll
            for (int mt = 0; mt < 4; mt++)
                ldsm_x4(a[mt][0], a[mt][1], a[mt][2], a[mt][3],
                        smem_u32(&As[cur][wmb + mt * 16 + arow][ks * 16 + acol8]));
#pragma unroll
            for (int nt = 0; nt < 4; nt++)
                ldsm_x2t(b[nt][0], b[nt][1],
                         smem_u32(&Bs[cur][ks * 16 + arow][wnb + nt * 8]));
#pragma unroll
            for (int mt = 0; mt < 4; mt++)
#pragma unroll
                for (int nt = 0; nt < 4; nt++)
                    mma16816(acc[mt][nt], a[mt], b[nt]);
        }
        __syncthreads();
    }

    // ---- epilogue: bias + relu -> g_F16 cols [0,512) fp16 only ----
    int gq = ln >> 2, tq = ln & 3;
#pragma unroll
    for (int mt = 0; mt < 4; mt++) {
        int r0 = bm + wmb + mt * 16 + gq;
        int r1 = r0 + 8;
#pragma unroll
        for (int nt = 0; nt < 4; nt++) {
            int c = bn + wnb + nt * 8 + tq * 2;
            float bx = bias[c], by = bias[c + 1];
            float* ac = acc[mt][nt];
            if (r0 < NN) {
                float ox = fmaxf(ac[0] + bx, 0.f), oy = fmaxf(ac[1] + by, 0.f);
                *(__half2*)(g_F16 + (size_t)r0 * HDIM + c) = __floats2half2_rn(ox, oy);
            }
            if (r1 < NN) {
                float ox = fmaxf(ac[2] + bx, 0.f), oy = fmaxf(ac[3] + by, 0.f);
                *(__half2*)(g_F16 + (size_t)r1 * HDIM + c) = __floats2half2_rn(ox, oy);
            }
        }
    }
}

// ---------------- SpMM (fp16 gather via LDG.128, fp32 accumulate) ------------
// out[r] = dinv[r]*(sum_c dinv[c]*v[c] + dinv[r]*v[r]); 64 threads per row.
__device__ __forceinline__ void h8f(uint4 p, float* v) {
    float2 q0 = __half22float2(*(__half2*)&p.x);
    float2 q1 = __half22float2(*(__half2*)&p.y);
    float2 q2 = __half22float2(*(__half2*)&p.z);
    float2 q3 = __half22float2(*(__half2*)&p.w);
    v[0] = q0.x; v[1] = q0.y; v[2] = q1.x; v[3] = q1.y;
    v[4] = q2.x; v[5] = q2.y; v[6] = q3.x; v[7] = q3.y;
}

template <int PASS>
__global__ void __launch_bounds__(64) k_spmm16() {
    const int INOFF  = (PASS == 1) ? 0   : 512;
    const int OUTOFF = (PASS == 1) ? 512 : 1024;
    int r = blockIdx.x;
    int f = threadIdx.x * 8;
    float di = g_dinv[r];
    const __half* __restrict__ base = g_F16 + INOFF + f;

    float acc[8], v[8];
    h8f(*(const uint4*)(base + (size_t)r * HDIM), v);
#pragma unroll
    for (int q = 0; q < 8; q++) acc[q] = di * v[q];

    int s = g_rowptr[r], e = g_rowptr[r + 1];
    int j = s;
    for (; j + 3 < e; j += 4) {
        int c0 = g_cols[j], c1 = g_cols[j + 1];
        int c2 = g_cols[j + 2], c3 = g_cols[j + 3];
        float w0 = g_dinv[c0], w1 = g_dinv[c1];
        float w2 = g_dinv[c2], w3 = g_dinv[c3];
        uint4 p0 = *(const uint4*)(base + (size_t)c0 * HDIM);
        uint4 p1 = *(const uint4*)(base + (size_t)c1 * HDIM);
        uint4 p2 = *(const uint4*)(base + (size_t)c2 * HDIM);
        uint4 p3 = *(const uint4*)(base + (size_t)c3 * HDIM);
        float v0[8], v1[8], v2[8], v3[8];
        h8f(p0, v0); h8f(p1, v1); h8f(p2, v2); h8f(p3, v3);
#pragma unroll
        for (int q = 0; q < 8; q++)
            acc[q] = fmaf(w0, v0[q], fmaf(w1, v1[q], fmaf(w2, v2[q], fmaf(w3, v3[q], acc[q]))));
    }
    for (; j < e; j++) {
        int c0 = g_cols[j];
        float w0 = g_dinv[c0];
        uint4 p0 = *(const uint4*)(base + (size_t)c0 * HDIM);
        float v0[8];
        h8f(p0, v0);
#pragma unroll
        for (int q = 0; q < 8; q++) acc[q] = fmaf(w0, v0[q], acc[q]);
    }
    uint4 o;
    __half2 h0 = __floats2half2_rn(di * acc[0], di * acc[1]);
    __half2 h1 = __floats2half2_rn(di * acc[2], di * acc[3]);
    __half2 h2 = __floats2half2_rn(di * acc[4], di * acc[5]);
    __half2 h3 = __floats2half2_rn(di * acc[6], di * acc[7]);
    o.x = *(uint32_t*)&h0; o.y = *(uint32_t*)&h1;
    o.z = *(uint32_t*)&h2; o.w = *(uint32_t*)&h3;
    *(uint4*)(g_F16 + (size_t)r * HDIM + OUTOFF + f) = o;
}

// ---------------- GEMM2 (tensor cores) + log_softmax fused -------------------
// out = log_softmax(F16 @ Wc16 + b2). 128 rows x 40 cols per block, 4 warps.
// Warp tile 32x40 (2 m16 x 5 n8). BK=32 double-buffered cp.async.
// log_softmax reduced in registers via quad shuffles (no smem staging).
__global__ void __launch_bounds__(128) k_gemm2(const float* __restrict__ bias,
                                               float* __restrict__ out) {
    __shared__ __align__(16) __half As[2][128][40];  // stride 80 B (5 mod 8 ✓)
    __shared__ __align__(16) __half Bs[2][32][56];   // stride 112 B (7 mod 8 ✓)

    int bm = blockIdx.x * 128;
    int tid = threadIdx.x;
    int wid = tid >> 5, ln = tid & 31;

    float acc[2][5][4];
#pragma unroll
    for (int mt = 0; mt < 2; mt++)
#pragma unroll
        for (int nt = 0; nt < 5; nt++)
#pragma unroll
            for (int q = 0; q < 4; q++) acc[mt][nt][q] = 0.f;

    auto cp_load = [&](int buf, int k0) {
        // A: 128 rows x 32 halves = 4 chunks/row -> 512 chunks / 128 thr = 4
#pragma unroll
        for (int l = 0; l < 4; l++) {
            int ch = tid + l * 128;
            int r = ch >> 2, c = (ch & 3) << 3;
            int gr = bm + r;
            const __half* src = g_F16 + ((gr < NN) ? ((size_t)gr * HDIM + k0 + c) : 0);
            cp16(smem_u32(&As[buf][r][c]), src, (gr < NN) ? 16 : 0);
        }
        // B: 32 rows x 40 halves = 5 chunks/row -> 160 chunks
#pragma unroll
        for (int l = 0; l < 2; l++) {
            int ch = tid + l * 128;
            if (ch < 160) {
                int r = ch / 5, c = (ch % 5) << 3;
                cp16(smem_u32(&Bs[buf][r][c]), g_Wc16 + (size_t)(k0 + r) * NCLS + c, 16);
            }
        }
    };

    int arow = ln & 15;
    int acol8 = (ln >> 4) << 3;

    cp_load(0, 0);
    asm volatile("cp.async.commit_group;");

    const int NKT = HDIM / 32;  // 48
    for (int kt = 0; kt < NKT; kt++) {
        int cur = kt & 1;
        if (kt + 1 < NKT) {
            cp_load(cur ^ 1, (kt + 1) * 32);
            asm volatile("cp.async.commit_group;");
            asm volatile("cp.async.wait_group 1;");
        } else {
            asm volatile("cp.async.wait_group 0;");
        }
        __syncthreads();
#pragma unroll
        for (int ks = 0; ks < 2; ks++) {
            uint32_t a[2][4], b[5][2];
#pragma unroll
            for (int mt = 0; mt < 2; mt++)
                ldsm_x4(a[mt][0], a[mt][1], a[mt][2], a[mt][3],
                        smem_u32(&As[cur][wid * 32 + mt * 16 + arow][ks * 16 + acol8]));
#pragma unroll
            for (int nt = 0; nt < 5; nt++)
                ldsm_x2t(b[nt][0], b[nt][1],
                         smem_u32(&Bs[cur][ks * 16 + arow][nt * 8]));
#pragma unroll
            for (int mt = 0; mt < 2; mt++)
#pragma unroll
                for (int nt = 0; nt < 5; nt++)
                    mma16816(acc[mt][nt], a[mt], b[nt]);
        }
        __syncthreads();
    }

    // ---- bias + register log_softmax + store ----
    int q = ln >> 2, tq = ln & 3;
#pragma unroll
    for (int nt = 0; nt < 5; nt++) {
        int c = nt * 8 + tq * 2;
        float bx = bias[c], by = bias[c + 1];
#pragma unroll
        for (int mt = 0; mt < 2; mt++) {
            acc[mt][nt][0] += bx; acc[mt][nt][1] += by;
            acc[mt][nt][2] += bx; acc[mt][nt][3] += by;
        }
    }
#pragma unroll
    for (int mt = 0; mt < 2; mt++) {
#pragma unroll
        for (int half = 0; half < 2; half++) {   // half=0: row q, half=1: row q+8
            int i0 = half * 2, i1 = half * 2 + 1;
            float mx = -1e30f;
#pragma unroll
            for (int nt = 0; nt < 5; nt++)
                mx = fmaxf(mx, fmaxf(acc[mt][nt][i0], acc[mt][nt][i1]));
            mx = fmaxf(mx, __shfl_xor_sync(0xffffffffu, mx, 1));
            mx = fmaxf(mx, __shfl_xor_sync(0xffffffffu, mx, 2));
            float sm = 0.f;
#pragma unroll
            for (int nt = 0; nt < 5; nt++)
                sm += expf(acc[mt][nt][i0] - mx) + expf(acc[mt][nt][i1] - mx);
            sm += __shfl_xor_sync(0xffffffffu, sm, 1);
            sm += __shfl_xor_sync(0xffffffffu, sm, 2);
            float lse = mx + logf(sm);
            int gr = bm + wid * 32 + mt * 16 + q + half * 8;
            if (gr < NN) {
#pragma unroll
                for (int nt = 0; nt < 5; nt++) {
                    int c = nt * 8 + tq * 2;
                    *(float2*)&out[(size_t)gr * NCLS + c] =
                        make_float2(acc[mt][nt][i0] - lse, acc[mt][nt][i1] - lse);
                }
            }
        }
    }
}

// ---------------- entry -----------------------------------------------------
extern "C" void kernel_launch(void* const* d_in, const int* in_sizes, int n_in,
                              void* d_out, int out_size) {
    const float* x    = (const float*)d_in[0];
    const int*   erow = (const int*)d_in[1];
    const int*   ecol = (const int*)d_in[2];
    const float* W1   = (const float*)d_in[3];
    const float* b1   = (const float*)d_in[4];
    const float* W2   = (const float*)d_in[5];
    const float* b2   = (const float*)d_in[6];
    float* out = (float*)d_out;
    (void)in_sizes; (void)n_in; (void)out_size;

    // 1: fp16 casts of x and W1
    const size_t ncast4 = (size_t)NN * FIN / 4 + (size_t)FIN * DIMF / 4;
    k_xcast<<<(unsigned)((ncast4 + 255) / 256), 256>>>(x, W1);

    // 2-3: preprocessing start
    k_zero_counts<<<(NN + 255) / 256, 256>>>();
    k_count<<<(NE + 255) / 256, 256>>>(erow, ecol);

    // 4: GEMM1 (tensor cores) — profiled slot
    dim3 g1(DIMF / 128, (NN + 127) / 128);
    k_gemm1<<<g1, 256>>>(b1);

    // 5-9: finish preprocessing
    k_scan_part<<<NBLK, 1024>>>();
    k_scan_bsum<<<1, 64>>>();
    k_scan_add<<<NBLK, 1024>>>();
    k_scatter<<<(NE + 255) / 256, 256>>>(erow, ecol);
    k_wc16<<<(HDIM * NCLS + 255) / 256, 256>>>(W2);

    // 10-11: SpMM passes (fp16 LDG.128 gathers, fp32 accum)
    k_spmm16<1><<<NN, 64>>>();
    k_spmm16<2><<<NN, 64>>>();

    // 12: GEMM2 (tensor cores) + log_softmax fused
    k_gemm2<<<(NN + 127) / 128, 128>>>(b2, out);
}

// round 10
// speedup vs baseline: 4.9038x; 1.0397x over previous
#include <cuda_runtime.h>
#include <cuda_fp16.h>
#include <cstdint>

// Problem constants (fixed by the dataset)
#define NN    50000      // nodes
#define NE    1600000    // edges
#define FIN   512        // input features
#define DIMF  512        // hidden dim
#define NCLS  40         // classes
#define HDIM  1536       // F16 = [ t(512) | s1(512) | s2(512) ]
#define NBLK  49         // scan blocks: 49*1024 >= 50000

// ---------------- scratch (device globals: no cudaMalloc allowed) ----------
__device__ __align__(128) __half g_F16[(size_t)NN * HDIM];  // ~150 MB features
__device__ __align__(128) __half g_x16[(size_t)NN * FIN];   // fp16 copy of x
__device__ __align__(128) __half g_w16[FIN * DIMF];         // fp16 copy of W1
__device__ __align__(128) __half g_Wc16[HDIM * NCLS];       // fp16 combined W2
__device__ float g_dinv[NN];
__device__ int   g_degc[NN];
__device__ int   g_rcnt[NN];
__device__ int   g_rowptr[NN + 1];
__device__ int   g_cursor[NN];
__device__ int   g_cols[NE];
__device__ int   g_bsum[NBLK];
__device__ int   g_boff[NBLK];

// ---------------- tensor-core helpers ----------------------------------------
__device__ __forceinline__ uint32_t smem_u32(const void* p) {
    return (uint32_t)__cvta_generic_to_shared(p);
}
__device__ __forceinline__ void ldsm_x4(uint32_t& r0, uint32_t& r1,
                                        uint32_t& r2, uint32_t& r3, uint32_t a) {
    asm volatile("ldmatrix.sync.aligned.m8n8.x4.shared.b16 {%0,%1,%2,%3}, [%4];"
                 : "=r"(r0), "=r"(r1), "=r"(r2), "=r"(r3) : "r"(a));
}
__device__ __forceinline__ void ldsm_x2t(uint32_t& r0, uint32_t& r1, uint32_t a) {
    asm volatile("ldmatrix.sync.aligned.m8n8.x2.trans.shared.b16 {%0,%1}, [%2];"
                 : "=r"(r0), "=r"(r1) : "r"(a));
}
__device__ __forceinline__ void mma16816(float* c, const uint32_t* a, const uint32_t* b) {
    asm volatile("mma.sync.aligned.m16n8k16.row.col.f32.f16.f16.f32 "
                 "{%0,%1,%2,%3}, {%4,%5,%6,%7}, {%8,%9}, {%0,%1,%2,%3};"
                 : "+f"(c[0]), "+f"(c[1]), "+f"(c[2]), "+f"(c[3])
                 : "r"(a[0]), "r"(a[1]), "r"(a[2]), "r"(a[3]), "r"(b[0]), "r"(b[1]));
}
__device__ __forceinline__ void cp16(uint32_t dst, const void* src, int src_bytes) {
    asm volatile("cp.async.cg.shared.global [%0], [%1], 16, %2;"
                 :: "r"(dst), "l"(src), "r"(src_bytes));
}

// ---------------- fp16 cast of x and W1 --------------------------------------
__global__ void k_xcast(const float* __restrict__ x, const float* __restrict__ W1) {
    size_t i = (size_t)blockIdx.x * blockDim.x + threadIdx.x;   // float4 index
    const size_t nx4 = (size_t)NN * FIN / 4;
    const size_t nw4 = (size_t)FIN * DIMF / 4;
    if (i < nx4) {
        float4 v = ((const float4*)x)[i];
        __half2 h0 = __floats2half2_rn(v.x, v.y);
        __half2 h1 = __floats2half2_rn(v.z, v.w);
        *(uint2*)(g_x16 + i * 4) = make_uint2(*(uint32_t*)&h0, *(uint32_t*)&h1);
    } else if (i < nx4 + nw4) {
        size_t j = i - nx4;
        float4 v = ((const float4*)W1)[j];
        __half2 h0 = __floats2half2_rn(v.x, v.y);
        __half2 h1 = __floats2half2_rn(v.z, v.w);
        *(uint2*)(g_w16 + j * 4) = make_uint2(*(uint32_t*)&h0, *(uint32_t*)&h1);
    }
}

// ---------------- graph preprocessing ---------------------------------------
__global__ void k_zero_counts() {
    int i = blockIdx.x * blockDim.x + threadIdx.x;
    if (i < NN) { g_degc[i] = 0; g_rcnt[i] = 0; g_cursor[i] = 0; }
}

__global__ void k_count(const int* __restrict__ erow, const int* __restrict__ ecol) {
    int e = blockIdx.x * blockDim.x + threadIdx.x;
    if (e < NE) {
        atomicAdd(&g_degc[ecol[e]], 1);
        atomicAdd(&g_rcnt[erow[e]], 1);
    }
}

__global__ void __launch_bounds__(1024) k_scan_part() {
    __shared__ int wsum[32];
    int lane = threadIdx.x & 31, wid = threadIdx.x >> 5;
    int i = blockIdx.x * 1024 + threadIdx.x;
    if (i < NN) g_dinv[i] = rsqrtf((float)(g_degc[i] + 1));  // +1 self loop
    int s = (i < NN) ? g_rcnt[i] : 0;
#pragma unroll
    for (int o = 1; o < 32; o <<= 1) {
        int t = __shfl_up_sync(0xffffffffu, s, o);
        if (lane >= o) s += t;
    }
    if (lane == 31) wsum[wid] = s;
    __syncthreads();
    if (wid == 0) {
        int ws = wsum[lane];
#pragma unroll
        for (int o = 1; o < 32; o <<= 1) {
            int t = __shfl_up_sync(0xffffffffu, ws, o);
            if (lane >= o) ws += t;
        }
        wsum[lane] = ws;
    }
    __syncthreads();
    s += (wid > 0 ? wsum[wid - 1] : 0);
    if (i < NN) g_rowptr[i + 1] = s;
    if (threadIdx.x == 1023) g_bsum[blockIdx.x] = s;
}

__global__ void k_scan_bsum() {
    __shared__ int sh[64];
    int t = threadIdx.x;
    int v = (t < NBLK) ? g_bsum[t] : 0;
    sh[t] = v;
    __syncthreads();
    for (int o = 1; o < 64; o <<= 1) {
        int u = (t >= o) ? sh[t - o] : 0;
        __syncthreads();
        sh[t] += u;
        __syncthreads();
    }
    if (t < NBLK) g_boff[t] = sh[t] - v;
}

__global__ void __launch_bounds__(1024) k_scan_add() {
    int i = blockIdx.x * 1024 + threadIdx.x;
    if (i < NN) g_rowptr[i + 1] += g_boff[blockIdx.x];
    if (i == 0) g_rowptr[0] = 0;
}

__global__ void k_scatter(const int* __restrict__ erow, const int* __restrict__ ecol) {
    int e = blockIdx.x * blockDim.x + threadIdx.x;
    if (e < NE) {
        int r = erow[e];
        int p = g_rowptr[r] + atomicAdd(&g_cursor[r], 1);
        g_cols[p] = ecol[e];
    }
}

// Combined classifier weight over [t | s1 | s2], cast to fp16
__global__ void k_wc16(const float* __restrict__ W2) {
    int i = blockIdx.x * blockDim.x + threadIdx.x;
    if (i >= HDIM * NCLS) return;
    const int S = 512 * NCLS;
    float v;
    if (i < S)          v = W2[i] + W2[i + S];
    else if (i < 2 * S) v = W2[i + S] + W2[i + 2 * S];
    else                v = W2[i + 2 * S];
    g_Wc16[i] = __float2half_rn(v);
}

// ---------------- GEMM1 (tensor cores): t = relu(x16 @ w16 + b1) ------------
__global__ void __launch_bounds__(256) k_gemm1(const float* __restrict__ bias) {
    __shared__ __align__(16) __half As[2][128][40];   // pad 40: row stride 80 B
    __shared__ __align__(16) __half Bs[2][32][136];   // pad 136: row stride 272 B

    int bm = blockIdx.y * 128;
    int bn = blockIdx.x * 128;
    int tid = threadIdx.x;
    int wid = tid >> 5, ln = tid & 31;
    int wmb = (wid & 1) * 64;
    int wnb = (wid >> 1) * 32;

    float acc[4][4][4];
#pragma unroll
    for (int mt = 0; mt < 4; mt++)
#pragma unroll
        for (int nt = 0; nt < 4; nt++)
#pragma unroll
            for (int q = 0; q < 4; q++) acc[mt][nt][q] = 0.f;

    auto cp_load = [&](int buf, int k0) {
#pragma unroll
        for (int l = 0; l < 2; l++) {
            int ch = tid + l * 256;
            int ar = ch >> 2, ak = (ch & 3) << 3;
            int gr = bm + ar;
            const __half* src = g_x16 + ((gr < NN) ? ((size_t)gr * FIN + k0 + ak) : 0);
            cp16(smem_u32(&As[buf][ar][ak]), src, (gr < NN) ? 16 : 0);
        }
#pragma unroll
        for (int l = 0; l < 2; l++) {
            int ch = tid + l * 256;
            int br = ch >> 4, bc = (ch & 15) << 3;
            cp16(smem_u32(&Bs[buf][br][bc]),
                 g_w16 + (size_t)(k0 + br) * DIMF + bn + bc, 16);
        }
    };

    int arow = ln & 15;
    int acol8 = (ln >> 4) << 3;

    cp_load(0, 0);
    asm volatile("cp.async.commit_group;");

    for (int kt = 0; kt < 16; kt++) {
        int cur = kt & 1;
        if (kt + 1 < 16) {
            cp_load(cur ^ 1, (kt + 1) * 32);
            asm volatile("cp.async.commit_group;");
            asm volatile("cp.async.wait_group 1;");
        } else {
            asm volatile("cp.async.wait_group 0;");
        }
        __syncthreads();
#pragma unroll
        for (int ks = 0; ks < 2; ks++) {
            uint32_t a[4][4], b[4][2];
#pragma unroll
            for (int mt = 0; mt < 4; mt++)
                ldsm_x4(a[mt][0], a[mt][1], a[mt][2], a[mt][3],
                        smem_u32(&As[cur][wmb + mt * 16 + arow][ks * 16 + acol8]));
#pragma unroll
            for (int nt = 0; nt < 4; nt++)
                ldsm_x2t(b[nt][0], b[nt][1],
                         smem_u32(&Bs[cur][ks * 16 + arow][wnb + nt * 8]));
#pragma unroll
            for (int mt = 0; mt < 4; mt++)
#pragma unroll
                for (int nt = 0; nt < 4; nt++)
                    mma16816(acc[mt][nt], a[mt], b[nt]);
        }
        __syncthreads();
    }

    // ---- epilogue: bias + relu -> g_F16 cols [0,512) fp16 ----
    int gq = ln >> 2, tq = ln & 3;
#pragma unroll
    for (int mt = 0; mt < 4; mt++) {
        int r0 = bm + wmb + mt * 16 + gq;
        int r1 = r0 + 8;
#pragma unroll
        for (int nt = 0; nt < 4; nt++) {
            int c = bn + wnb + nt * 8 + tq * 2;
            float bx = bias[c], by = bias[c + 1];
            float* ac = acc[mt][nt];
            if (r0 < NN) {
                float ox = fmaxf(ac[0] + bx, 0.f), oy = fmaxf(ac[1] + by, 0.f);
                *(__half2*)(g_F16 + (size_t)r0 * HDIM + c) = __floats2half2_rn(ox, oy);
            }
            if (r1 < NN) {
                float ox = fmaxf(ac[2] + bx, 0.f), oy = fmaxf(ac[3] + by, 0.f);
                *(__half2*)(g_F16 + (size_t)r1 * HDIM + c) = __floats2half2_rn(ox, oy);
            }
        }
    }
}

// ---------------- SpMM (fp16 gather via LDG.128, fp32 accumulate) ------------
__device__ __forceinline__ void h8f(uint4 p, float* v) {
    float2 q0 = __half22float2(*(__half2*)&p.x);
    float2 q1 = __half22float2(*(__half2*)&p.y);
    float2 q2 = __half22float2(*(__half2*)&p.z);
    float2 q3 = __half22float2(*(__half2*)&p.w);
    v[0] = q0.x; v[1] = q0.y; v[2] = q1.x; v[3] = q1.y;
    v[4] = q2.x; v[5] = q2.y; v[6] = q3.x; v[7] = q3.y;
}

template <int PASS>
__global__ void __launch_bounds__(64) k_spmm16() {
    const int INOFF  = (PASS == 1) ? 0   : 512;
    const int OUTOFF = (PASS == 1) ? 512 : 1024;
    int r = blockIdx.x;
    int f = threadIdx.x * 8;
    float di = g_dinv[r];
    const __half* __restrict__ base = g_F16 + INOFF + f;

    float acc[8], v[8];
    h8f(*(const uint4*)(base + (size_t)r * HDIM), v);
#pragma unroll
    for (int q = 0; q < 8; q++) acc[q] = di * v[q];

    int s = g_rowptr[r], e = g_rowptr[r + 1];
    int j = s;
    for (; j + 3 < e; j += 4) {
        int c0 = g_cols[j], c1 = g_cols[j + 1];
        int c2 = g_cols[j + 2], c3 = g_cols[j + 3];
        float w0 = g_dinv[c0], w1 = g_dinv[c1];
        float w2 = g_dinv[c2], w3 = g_dinv[c3];
        uint4 p0 = *(const uint4*)(base + (size_t)c0 * HDIM);
        uint4 p1 = *(const uint4*)(base + (size_t)c1 * HDIM);
        uint4 p2 = *(const uint4*)(base + (size_t)c2 * HDIM);
        uint4 p3 = *(const uint4*)(base + (size_t)c3 * HDIM);
        float v0[8], v1[8], v2[8], v3[8];
        h8f(p0, v0); h8f(p1, v1); h8f(p2, v2); h8f(p3, v3);
#pragma unroll
        for (int q = 0; q < 8; q++)
            acc[q] = fmaf(w0, v0[q], fmaf(w1, v1[q], fmaf(w2, v2[q], fmaf(w3, v3[q], acc[q]))));
    }
    for (; j < e; j++) {
        int c0 = g_cols[j];
        float w0 = g_dinv[c0];
        uint4 p0 = *(const uint4*)(base + (size_t)c0 * HDIM);
        float v0[8];
        h8f(p0, v0);
#pragma unroll
        for (int q = 0; q < 8; q++) acc[q] = fmaf(w0, v0[q], acc[q]);
    }
    uint4 o;
    __half2 h0 = __floats2half2_rn(di * acc[0], di * acc[1]);
    __half2 h1 = __floats2half2_rn(di * acc[2], di * acc[3]);
    __half2 h2 = __floats2half2_rn(di * acc[4], di * acc[5]);
    __half2 h3 = __floats2half2_rn(di * acc[6], di * acc[7]);
    o.x = *(uint32_t*)&h0; o.y = *(uint32_t*)&h1;
    o.z = *(uint32_t*)&h2; o.w = *(uint32_t*)&h3;
    *(uint4*)(g_F16 + (size_t)r * HDIM + OUTOFF + f) = o;
}

// ---------------- GEMM2 (tensor cores) + log_softmax fused -------------------
__global__ void __launch_bounds__(128) k_gemm2(const float* __restrict__ bias,
                                               float* __restrict__ out) {
    __shared__ __align__(16) __half As[2][128][40];  // stride 80 B
    __shared__ __align__(16) __half Bs[2][32][56];   // stride 112 B

    int bm = blockIdx.x * 128;
    int tid = threadIdx.x;
    int wid = tid >> 5, ln = tid & 31;

    float acc[2][5][4];
#pragma unroll
    for (int mt = 0; mt < 2; mt++)
#pragma unroll
        for (int nt = 0; nt < 5; nt++)
#pragma unroll
            for (int q = 0; q < 4; q++) acc[mt][nt][q] = 0.f;

    auto cp_load = [&](int buf, int k0) {
#pragma unroll
        for (int l = 0; l < 4; l++) {
            int ch = tid + l * 128;
            int r = ch >> 2, c = (ch & 3) << 3;
            int gr = bm + r;
            const __half* src = g_F16 + ((gr < NN) ? ((size_t)gr * HDIM + k0 + c) : 0);
            cp16(smem_u32(&As[buf][r][c]), src, (gr < NN) ? 16 : 0);
        }
#pragma unroll
        for (int l = 0; l < 2; l++) {
            int ch = tid + l * 128;
            if (ch < 160) {
                int r = ch / 5, c = (ch % 5) << 3;
                cp16(smem_u32(&Bs[buf][r][c]), g_Wc16 + (size_t)(k0 + r) * NCLS + c, 16);
            }
        }
    };

    int arow = ln & 15;
    int acol8 = (ln >> 4) << 3;

    cp_load(0, 0);
    asm volatile("cp.async.commit_group;");

    const int NKT = HDIM / 32;  // 48
    for (int kt = 0; kt < NKT; kt++) {
        int cur = kt & 1;
        if (kt + 1 < NKT) {
            cp_load(cur ^ 1, (kt + 1) * 32);
            asm volatile("cp.async.commit_group;");
            asm volatile("cp.async.wait_group 1;");
        } else {
            asm volatile("cp.async.wait_group 0;");
        }
        __syncthreads();
#pragma unroll
        for (int ks = 0; ks < 2; ks++) {
            uint32_t a[2][4], b[5][2];
#pragma unroll
            for (int mt = 0; mt < 2; mt++)
                ldsm_x4(a[mt][0], a[mt][1], a[mt][2], a[mt][3],
                        smem_u32(&As[cur][wid * 32 + mt * 16 + arow][ks * 16 + acol8]));
#pragma unroll
            for (int nt = 0; nt < 5; nt++)
                ldsm_x2t(b[nt][0], b[nt][1],
                         smem_u32(&Bs[cur][ks * 16 + arow][nt * 8]));
#pragma unroll
            for (int mt = 0; mt < 2; mt++)
#pragma unroll
                for (int nt = 0; nt < 5; nt++)
                    mma16816(acc[mt][nt], a[mt], b[nt]);
        }
        __syncthreads();
    }

    // ---- bias + register log_softmax + store ----
    int q = ln >> 2, tq = ln & 3;
#pragma unroll
    for (int nt = 0; nt < 5; nt++) {
        int c = nt * 8 + tq * 2;
        float bx = bias[c], by = bias[c + 1];
#pragma unroll
        for (int mt = 0; mt < 2; mt++) {
            acc[mt][nt][0] += bx; acc[mt][nt][1] += by;
            acc[mt][nt][2] += bx; acc[mt][nt][3] += by;
        }
    }
#pragma unroll
    for (int mt = 0; mt < 2; mt++) {
#pragma unroll
        for (int half = 0; half < 2; half++) {
            int i0 = half * 2, i1 = half * 2 + 1;
            float mx = -1e30f;
#pragma unroll
            for (int nt = 0; nt < 5; nt++)
                mx = fmaxf(mx, fmaxf(acc[mt][nt][i0], acc[mt][nt][i1]));
            mx = fmaxf(mx, __shfl_xor_sync(0xffffffffu, mx, 1));
            mx = fmaxf(mx, __shfl_xor_sync(0xffffffffu, mx, 2));
            float sm = 0.f;
#pragma unroll
            for (int nt = 0; nt < 5; nt++)
                sm += expf(acc[mt][nt][i0] - mx) + expf(acc[mt][nt][i1] - mx);
            sm += __shfl_xor_sync(0xffffffffu, sm, 1);
            sm += __shfl_xor_sync(0xffffffffu, sm, 2);
            float lse = mx + logf(sm);
            int gr = bm + wid * 32 + mt * 16 + q + half * 8;
            if (gr < NN) {
#pragma unroll
                for (int nt = 0; nt < 5; nt++) {
                    int c = nt * 8 + tq * 2;
                    *(float2*)&out[(size_t)gr * NCLS + c] =
                        make_float2(acc[mt][nt][i0] - lse, acc[mt][nt][i1] - lse);
                }
            }
        }
    }
}

// ---------------- entry -----------------------------------------------------
// Dependency DAG:
//   Branch A (capture stream): xcast -> gemm1           (needs x, W1)
//   Branch B (side stream):    zero -> count -> scan -> scatter, wc16
//   Join: spmm1 -> spmm2 -> gemm2 on capture stream.
// Fork/join via events is the documented cross-stream graph-capture pattern;
// streams/events are host objects created once (no device memory involved).
extern "C" void kernel_launch(void* const* d_in, const int* in_sizes, int n_in,
                              void* d_out, int out_size) {
    const float* x    = (const float*)d_in[0];
    const int*   erow = (const int*)d_in[1];
    const int*   ecol = (const int*)d_in[2];
    const float* W1   = (const float*)d_in[3];
    const float* b1   = (const float*)d_in[4];
    const float* W2   = (const float*)d_in[5];
    const float* b2   = (const float*)d_in[6];
    float* out = (float*)d_out;
    (void)in_sizes; (void)n_in; (void)out_size;

    static cudaStream_t sB = nullptr;
    static cudaEvent_t evFork = nullptr, evJoin = nullptr;
    if (sB == nullptr) {
        cudaStreamCreateWithFlags(&sB, cudaStreamNonBlocking);
        cudaEventCreateWithFlags(&evFork, cudaEventDisableTiming);
        cudaEventCreateWithFlags(&evJoin, cudaEventDisableTiming);
    }
    cudaStream_t s0 = 0;   // capture (default) stream

    // ---- fork ----
    cudaEventRecord(evFork, s0);
    cudaStreamWaitEvent(sB, evFork, 0);

    // Branch B (side stream): graph preprocessing + Wc fold
    k_zero_counts<<<(NN + 255) / 256, 256, 0, sB>>>();            // launch 1
    k_count<<<(NE + 255) / 256, 256, 0, sB>>>(erow, ecol);        // launch 2

    // Branch A (capture stream): cast + GEMM1 (launch 4 = profiled slot)
    const size_t ncast4 = (size_t)NN * FIN / 4 + (size_t)FIN * DIMF / 4;
    k_xcast<<<(unsigned)((ncast4 + 255) / 256), 256, 0, s0>>>(x, W1); // launch 3
    dim3 g1(DIMF / 128, (NN + 127) / 128);
    k_gemm1<<<g1, 256, 0, s0>>>(b1);                              // launch 4

    // Branch B continued
    k_scan_part<<<NBLK, 1024, 0, sB>>>();
    k_scan_bsum<<<1, 64, 0, sB>>>();
    k_scan_add<<<NBLK, 1024, 0, sB>>>();
    k_scatter<<<(NE + 255) / 256, 256, 0, sB>>>(erow, ecol);
    k_wc16<<<(HDIM * NCLS + 255) / 256, 256, 0, sB>>>(W2);

    // ---- join ----
    cudaEventRecord(evJoin, sB);
    cudaStreamWaitEvent(s0, evJoin, 0);

    // Serial tail on capture stream
    k_spmm16<1><<<NN, 64, 0, s0>>>();
    k_spmm16<2><<<NN, 64, 0, s0>>>();
    k_gemm2<<<(NN + 127) / 128, 128, 0, s0>>>(b2, out);
}

// round 11
// speedup vs baseline: 4.9063x; 1.0005x over previous
#include <cuda_runtime.h>
#include <cuda_fp16.h>
#include <cstdint>

// Problem constants (fixed by the dataset)
#define NN    50000      // nodes
#define NE    1600000    // edges
#define FIN   512        // input features
#define DIMF  512        // hidden dim
#define NCLS  40         // classes
#define HDIM  1536       // F16 = [ t(512) | s1(512) | s2(512) ]
#define NBLK  49         // scan blocks: 49*1024 >= 50000

// ---------------- scratch (device globals: no cudaMalloc allowed) ----------
__device__ __align__(128) __half g_F16[(size_t)NN * HDIM];  // ~150 MB features
__device__ __align__(128) __half g_x16[(size_t)NN * FIN];   // fp16 copy of x
__device__ __align__(128) __half g_w16[FIN * DIMF];         // fp16 copy of W1
__device__ __align__(128) __half g_Wc16[HDIM * NCLS];       // fp16 combined W2
__device__ float g_dinv[NN];
__device__ int   g_degc[NN];
__device__ int   g_rcnt[NN];
__device__ int   g_rowptr[NN + 1];
__device__ int   g_cursor[NN];
__device__ int   g_cols[NE];
__device__ int   g_bsum[NBLK];
__device__ int   g_boff[NBLK];

// ---------------- tensor-core helpers ----------------------------------------
__device__ __forceinline__ uint32_t smem_u32(const void* p) {
    return (uint32_t)__cvta_generic_to_shared(p);
}
__device__ __forceinline__ void ldsm_x4(uint32_t& r0, uint32_t& r1,
                                        uint32_t& r2, uint32_t& r3, uint32_t a) {
    asm volatile("ldmatrix.sync.aligned.m8n8.x4.shared.b16 {%0,%1,%2,%3}, [%4];"
                 : "=r"(r0), "=r"(r1), "=r"(r2), "=r"(r3) : "r"(a));
}
__device__ __forceinline__ void ldsm_x2t(uint32_t& r0, uint32_t& r1, uint32_t a) {
    asm volatile("ldmatrix.sync.aligned.m8n8.x2.trans.shared.b16 {%0,%1}, [%2];"
                 : "=r"(r0), "=r"(r1) : "r"(a));
}
__device__ __forceinline__ void mma16816(float* c, const uint32_t* a, const uint32_t* b) {
    asm volatile("mma.sync.aligned.m16n8k16.row.col.f32.f16.f16.f32 "
                 "{%0,%1,%2,%3}, {%4,%5,%6,%7}, {%8,%9}, {%0,%1,%2,%3};"
                 : "+f"(c[0]), "+f"(c[1]), "+f"(c[2]), "+f"(c[3])
                 : "r"(a[0]), "r"(a[1]), "r"(a[2]), "r"(a[3]), "r"(b[0]), "r"(b[1]));
}
__device__ __forceinline__ void cp16(uint32_t dst, const void* src, int src_bytes) {
    asm volatile("cp.async.cg.shared.global [%0], [%1], 16, %2;"
                 :: "r"(dst), "l"(src), "r"(src_bytes));
}

// ---------------- fp16 cast of x and W1 --------------------------------------
__global__ void k_xcast(const float* __restrict__ x, const float* __restrict__ W1) {
    size_t i = (size_t)blockIdx.x * blockDim.x + threadIdx.x;   // float4 index
    const size_t nx4 = (size_t)NN * FIN / 4;
    const size_t nw4 = (size_t)FIN * DIMF / 4;
    if (i < nx4) {
        float4 v = ((const float4*)x)[i];
        __half2 h0 = __floats2half2_rn(v.x, v.y);
        __half2 h1 = __floats2half2_rn(v.z, v.w);
        *(uint2*)(g_x16 + i * 4) = make_uint2(*(uint32_t*)&h0, *(uint32_t*)&h1);
    } else if (i < nx4 + nw4) {
        size_t j = i - nx4;
        float4 v = ((const float4*)W1)[j];
        __half2 h0 = __floats2half2_rn(v.x, v.y);
        __half2 h1 = __floats2half2_rn(v.z, v.w);
        *(uint2*)(g_w16 + j * 4) = make_uint2(*(uint32_t*)&h0, *(uint32_t*)&h1);
    }
}

// ---------------- graph preprocessing ---------------------------------------
__global__ void k_zero_counts() {
    int i = blockIdx.x * blockDim.x + threadIdx.x;
    if (i < NN) { g_degc[i] = 0; g_rcnt[i] = 0; g_cursor[i] = 0; }
}

__global__ void k_count(const int* __restrict__ erow, const int* __restrict__ ecol) {
    int e = blockIdx.x * blockDim.x + threadIdx.x;
    if (e < NE) {
        atomicAdd(&g_degc[ecol[e]], 1);
        atomicAdd(&g_rcnt[erow[e]], 1);
    }
}

__global__ void __launch_bounds__(1024) k_scan_part() {
    __shared__ int wsum[32];
    int lane = threadIdx.x & 31, wid = threadIdx.x >> 5;
    int i = blockIdx.x * 1024 + threadIdx.x;
    if (i < NN) g_dinv[i] = rsqrtf((float)(g_degc[i] + 1));  // +1 self loop
    int s = (i < NN) ? g_rcnt[i] : 0;
#pragma unroll
    for (int o = 1; o < 32; o <<= 1) {
        int t = __shfl_up_sync(0xffffffffu, s, o);
        if (lane >= o) s += t;
    }
    if (lane == 31) wsum[wid] = s;
    __syncthreads();
    if (wid == 0) {
        int ws = wsum[lane];
#pragma unroll
        for (int o = 1; o < 32; o <<= 1) {
            int t = __shfl_up_sync(0xffffffffu, ws, o);
            if (lane >= o) ws += t;
        }
        wsum[lane] = ws;
    }
    __syncthreads();
    s += (wid > 0 ? wsum[wid - 1] : 0);
    if (i < NN) g_rowptr[i + 1] = s;
    if (threadIdx.x == 1023) g_bsum[blockIdx.x] = s;
}

__global__ void k_scan_bsum() {
    __shared__ int sh[64];
    int t = threadIdx.x;
    int v = (t < NBLK) ? g_bsum[t] : 0;
    sh[t] = v;
    __syncthreads();
    for (int o = 1; o < 64; o <<= 1) {
        int u = (t >= o) ? sh[t - o] : 0;
        __syncthreads();
        sh[t] += u;
        __syncthreads();
    }
    if (t < NBLK) g_boff[t] = sh[t] - v;
}

__global__ void __launch_bounds__(1024) k_scan_add() {
    int i = blockIdx.x * 1024 + threadIdx.x;
    if (i < NN) g_rowptr[i + 1] += g_boff[blockIdx.x];
    if (i == 0) g_rowptr[0] = 0;
}

__global__ void k_scatter(const int* __restrict__ erow, const int* __restrict__ ecol) {
    int e = blockIdx.x * blockDim.x + threadIdx.x;
    if (e < NE) {
        int r = erow[e];
        int p = g_rowptr[r] + atomicAdd(&g_cursor[r], 1);
        g_cols[p] = ecol[e];
    }
}

// Combined classifier weight over [t | s1 | s2], cast to fp16
__global__ void k_wc16(const float* __restrict__ W2) {
    int i = blockIdx.x * blockDim.x + threadIdx.x;
    if (i >= HDIM * NCLS) return;
    const int S = 512 * NCLS;
    float v;
    if (i < S)          v = W2[i] + W2[i + S];
    else if (i < 2 * S) v = W2[i + S] + W2[i + 2 * S];
    else                v = W2[i + 2 * S];
    g_Wc16[i] = __float2half_rn(v);
}

// ---------------- GEMM1 (tensor cores): t = relu(x16 @ w16 + b1) ------------
__global__ void __launch_bounds__(256) k_gemm1(const float* __restrict__ bias) {
    __shared__ __align__(16) __half As[2][128][40];   // pad 40: row stride 80 B
    __shared__ __align__(16) __half Bs[2][32][136];   // pad 136: row stride 272 B

    int bm = blockIdx.y * 128;
    int bn = blockIdx.x * 128;
    int tid = threadIdx.x;
    int wid = tid >> 5, ln = tid & 31;
    int wmb = (wid & 1) * 64;
    int wnb = (wid >> 1) * 32;

    float acc[4][4][4];
#pragma unroll
    for (int mt = 0; mt < 4; mt++)
#pragma unroll
        for (int nt = 0; nt < 4; nt++)
#pragma unroll
            for (int q = 0; q < 4; q++) acc[mt][nt][q] = 0.f;

    auto cp_load = [&](int buf, int k0) {
#pragma unroll
        for (int l = 0; l < 2; l++) {
            int ch = tid + l * 256;
            int ar = ch >> 2, ak = (ch & 3) << 3;
            int gr = bm + ar;
            const __half* src = g_x16 + ((gr < NN) ? ((size_t)gr * FIN + k0 + ak) : 0);
            cp16(smem_u32(&As[buf][ar][ak]), src, (gr < NN) ? 16 : 0);
        }
#pragma unroll
        for (int l = 0; l < 2; l++) {
            int ch = tid + l * 256;
            int br = ch >> 4, bc = (ch & 15) << 3;
            cp16(smem_u32(&Bs[buf][br][bc]),
                 g_w16 + (size_t)(k0 + br) * DIMF + bn + bc, 16);
        }
    };

    int arow = ln & 15;
    int acol8 = (ln >> 4) << 3;

    cp_load(0, 0);
    asm volatile("cp.async.commit_group;");

    for (int kt = 0; kt < 16; kt++) {
        int cur = kt & 1;
        if (kt + 1 < 16) {
            cp_load(cur ^ 1, (kt + 1) * 32);
            asm volatile("cp.async.commit_group;");
            asm volatile("cp.async.wait_group 1;");
        } else {
            asm volatile("cp.async.wait_group 0;");
        }
        __syncthreads();
#pragma unroll
        for (int ks = 0; ks < 2; ks++) {
            uint32_t a[4][4], b[4][2];
#pragma unroll
            for (int mt = 0; mt < 4; mt++)
                ldsm_x4(a[mt][0], a[mt][1], a[mt][2], a[mt][3],
                        smem_u32(&As[cur][wmb + mt * 16 + arow][ks * 16 + acol8]));
#pragma unroll
            for (int nt = 0; nt < 4; nt++)
                ldsm_x2t(b[nt][0], b[nt][1],
                         smem_u32(&Bs[cur][ks * 16 + arow][wnb + nt * 8]));
#pragma unroll
            for (int mt = 0; mt < 4; mt++)
#pragma unroll
                for (int nt = 0; nt < 4; nt++)
                    mma16816(acc[mt][nt], a[mt], b[nt]);
        }
        __syncthreads();
    }

    // ---- epilogue: bias + relu -> g_F16 cols [0,512) fp16 ----
    int gq = ln >> 2, tq = ln & 3;
#pragma unroll
    for (int mt = 0; mt < 4; mt++) {
        int r0 = bm + wmb + mt * 16 + gq;
        int r1 = r0 + 8;
#pragma unroll
        for (int nt = 0; nt < 4; nt++) {
            int c = bn + wnb + nt * 8 + tq * 2;
            float bx = bias[c], by = bias[c + 1];
            float* ac = acc[mt][nt];
            if (r0 < NN) {
                float ox = fmaxf(ac[0] + bx, 0.f), oy = fmaxf(ac[1] + by, 0.f);
                *(__half2*)(g_F16 + (size_t)r0 * HDIM + c) = __floats2half2_rn(ox, oy);
            }
            if (r1 < NN) {
                float ox = fmaxf(ac[2] + bx, 0.f), oy = fmaxf(ac[3] + by, 0.f);
                *(__half2*)(g_F16 + (size_t)r1 * HDIM + c) = __floats2half2_rn(ox, oy);
            }
        }
    }
}

// ---------------- SpMM (fp16 gather via LDG.128, fp32 accumulate) ------------
__device__ __forceinline__ void h8f(uint4 p, float* v) {
    float2 q0 = __half22float2(*(__half2*)&p.x);
    float2 q1 = __half22float2(*(__half2*)&p.y);
    float2 q2 = __half22float2(*(__half2*)&p.z);
    float2 q3 = __half22float2(*(__half2*)&p.w);
    v[0] = q0.x; v[1] = q0.y; v[2] = q1.x; v[3] = q1.y;
    v[4] = q2.x; v[5] = q2.y; v[6] = q3.x; v[7] = q3.y;
}

template <int PASS>
__global__ void __launch_bounds__(64) k_spmm16() {
    const int INOFF  = (PASS == 1) ? 0   : 512;
    const int OUTOFF = (PASS == 1) ? 512 : 1024;
    int r = blockIdx.x;
    int f = threadIdx.x * 8;
    float di = g_dinv[r];
    const __half* __restrict__ base = g_F16 + INOFF + f;

    float acc[8], v[8];
    h8f(*(const uint4*)(base + (size_t)r * HDIM), v);
#pragma unroll
    for (int q = 0; q < 8; q++) acc[q] = di * v[q];

    int s = g_rowptr[r], e = g_rowptr[r + 1];
    int j = s;
    for (; j + 3 < e; j += 4) {
        int c0 = g_cols[j], c1 = g_cols[j + 1];
        int c2 = g_cols[j + 2], c3 = g_cols[j + 3];
        float w0 = g_dinv[c0], w1 = g_dinv[c1];
        float w2 = g_dinv[c2], w3 = g_dinv[c3];
        uint4 p0 = *(const uint4*)(base + (size_t)c0 * HDIM);
        uint4 p1 = *(const uint4*)(base + (size_t)c1 * HDIM);
        uint4 p2 = *(const uint4*)(base + (size_t)c2 * HDIM);
        uint4 p3 = *(const uint4*)(base + (size_t)c3 * HDIM);
        float v0[8], v1[8], v2[8], v3[8];
        h8f(p0, v0); h8f(p1, v1); h8f(p2, v2); h8f(p3, v3);
#pragma unroll
        for (int q = 0; q < 8; q++)
            acc[q] = fmaf(w0, v0[q], fmaf(w1, v1[q], fmaf(w2, v2[q], fmaf(w3, v3[q], acc[q]))));
    }
    for (; j < e; j++) {
        int c0 = g_cols[j];
        float w0 = g_dinv[c0];
        uint4 p0 = *(const uint4*)(base + (size_t)c0 * HDIM);
        float v0[8];
        h8f(p0, v0);
#pragma unroll
        for (int q = 0; q < 8; q++) acc[q] = fmaf(w0, v0[q], acc[q]);
    }
    uint4 o;
    __half2 h0 = __floats2half2_rn(di * acc[0], di * acc[1]);
    __half2 h1 = __floats2half2_rn(di * acc[2], di * acc[3]);
    __half2 h2 = __floats2half2_rn(di * acc[4], di * acc[5]);
    __half2 h3 = __floats2half2_rn(di * acc[6], di * acc[7]);
    o.x = *(uint32_t*)&h0; o.y = *(uint32_t*)&h1;
    o.z = *(uint32_t*)&h2; o.w = *(uint32_t*)&h3;
    *(uint4*)(g_F16 + (size_t)r * HDIM + OUTOFF + f) = o;
}

// ---------------- GEMM2 (tensor cores) + log_softmax fused -------------------
__global__ void __launch_bounds__(128) k_gemm2(const float* __restrict__ bias,
                                               float* __restrict__ out) {
    __shared__ __align__(16) __half As[2][128][40];  // stride 80 B
    __shared__ __align__(16) __half Bs[2][32][56];   // stride 112 B

    int bm = blockIdx.x * 128;
    int tid = threadIdx.x;
    int wid = tid >> 5, ln = tid & 31;

    float acc[2][5][4];
#pragma unroll
    for (int mt = 0; mt < 2; mt++)
#pragma unroll
        for (int nt = 0; nt < 5; nt++)
#pragma unroll
            for (int q = 0; q < 4; q++) acc[mt][nt][q] = 0.f;

    auto cp_load = [&](int buf, int k0) {
#pragma unroll
        for (int l = 0; l < 4; l++) {
            int ch = tid + l * 128;
            int r = ch >> 2, c = (ch & 3) << 3;
            int gr = bm + r;
            const __half* src = g_F16 + ((gr < NN) ? ((size_t)gr * HDIM + k0 + c) : 0);
            cp16(smem_u32(&As[buf][r][c]), src, (gr < NN) ? 16 : 0);
        }
#pragma unroll
        for (int l = 0; l < 2; l++) {
            int ch = tid + l * 128;
            if (ch < 160) {
                int r = ch / 5, c = (ch % 5) << 3;
                cp16(smem_u32(&Bs[buf][r][c]), g_Wc16 + (size_t)(k0 + r) * NCLS + c, 16);
            }
        }
    };

    int arow = ln & 15;
    int acol8 = (ln >> 4) << 3;

    cp_load(0, 0);
    asm volatile("cp.async.commit_group;");

    const int NKT = HDIM / 32;  // 48
    for (int kt = 0; kt < NKT; kt++) {
        int cur = kt & 1;
        if (kt + 1 < NKT) {
            cp_load(cur ^ 1, (kt + 1) * 32);
            asm volatile("cp.async.commit_group;");
            asm volatile("cp.async.wait_group 1;");
        } else {
            asm volatile("cp.async.wait_group 0;");
        }
        __syncthreads();
#pragma unroll
        for (int ks = 0; ks < 2; ks++) {
            uint32_t a[2][4], b[5][2];
#pragma unroll
            for (int mt = 0; mt < 2; mt++)
                ldsm_x4(a[mt][0], a[mt][1], a[mt][2], a[mt][3],
                        smem_u32(&As[cur][wid * 32 + mt * 16 + arow][ks * 16 + acol8]));
#pragma unroll
            for (int nt = 0; nt < 5; nt++)
                ldsm_x2t(b[nt][0], b[nt][1],
                         smem_u32(&Bs[cur][ks * 16 + arow][nt * 8]));
#pragma unroll
            for (int mt = 0; mt < 2; mt++)
#pragma unroll
                for (int nt = 0; nt < 5; nt++)
                    mma16816(acc[mt][nt], a[mt], b[nt]);
        }
        __syncthreads();
    }

    // ---- bias + register log_softmax + store ----
    int q = ln >> 2, tq = ln & 3;
#pragma unroll
    for (int nt = 0; nt < 5; nt++) {
        int c = nt * 8 + tq * 2;
        float bx = bias[c], by = bias[c + 1];
#pragma unroll
        for (int mt = 0; mt < 2; mt++) {
            acc[mt][nt][0] += bx; acc[mt][nt][1] += by;
            acc[mt][nt][2] += bx; acc[mt][nt][3] += by;
        }
    }
#pragma unroll
    for (int mt = 0; mt < 2; mt++) {
#pragma unroll
        for (int half = 0; half < 2; half++) {
            int i0 = half * 2, i1 = half * 2 + 1;
            float mx = -1e30f;
#pragma unroll
            for (int nt = 0; nt < 5; nt++)
                mx = fmaxf(mx, fmaxf(acc[mt][nt][i0], acc[mt][nt][i1]));
            mx = fmaxf(mx, __shfl_xor_sync(0xffffffffu, mx, 1));
            mx = fmaxf(mx, __shfl_xor_sync(0xffffffffu, mx, 2));
            float sm = 0.f;
#pragma unroll
            for (int nt = 0; nt < 5; nt++)
                sm += expf(acc[mt][nt][i0] - mx) + expf(acc[mt][nt][i1] - mx);
            sm += __shfl_xor_sync(0xffffffffu, sm, 1);
            sm += __shfl_xor_sync(0xffffffffu, sm, 2);
            float lse = mx + logf(sm);
            int gr = bm + wid * 32 + mt * 16 + q + half * 8;
            if (gr < NN) {
#pragma unroll
                for (int nt = 0; nt < 5; nt++) {
                    int c = nt * 8 + tq * 2;
                    *(float2*)&out[(size_t)gr * NCLS + c] =
                        make_float2(acc[mt][nt][i0] - lse, acc[mt][nt][i1] - lse);
                }
            }
        }
    }
}

// ---------------- entry -----------------------------------------------------
// Dependency DAG:
//   Branch A (capture stream): xcast -> gemm1           (needs x, W1)
//   Branch B (side stream):    zero -> count -> scan -> scatter, wc16
//   Join: spmm1 -> spmm2 -> gemm2 on capture stream.
// Fork/join via events is the documented cross-stream graph-capture pattern;
// streams/events are host objects created once (no device memory involved).
extern "C" void kernel_launch(void* const* d_in, const int* in_sizes, int n_in,
                              void* d_out, int out_size) {
    const float* x    = (const float*)d_in[0];
    const int*   erow = (const int*)d_in[1];
    const int*   ecol = (const int*)d_in[2];
    const float* W1   = (const float*)d_in[3];
    const float* b1   = (const float*)d_in[4];
    const float* W2   = (const float*)d_in[5];
    const float* b2   = (const float*)d_in[6];
    float* out = (float*)d_out;
    (void)in_sizes; (void)n_in; (void)out_size;

    static cudaStream_t sB = nullptr;
    static cudaEvent_t evFork = nullptr, evJoin = nullptr;
    if (sB == nullptr) {
        cudaStreamCreateWithFlags(&sB, cudaStreamNonBlocking);
        cudaEventCreateWithFlags(&evFork, cudaEventDisableTiming);
        cudaEventCreateWithFlags(&evJoin, cudaEventDisableTiming);
    }
    cudaStream_t s0 = 0;   // capture (default) stream

    // ---- fork ----
    cudaEventRecord(evFork, s0);
    cudaStreamWaitEvent(sB, evFork, 0);

    // Branch B (side stream): graph preprocessing + Wc fold
    k_zero_counts<<<(NN + 255) / 256, 256, 0, sB>>>();            // launch 1
    k_count<<<(NE + 255) / 256, 256, 0, sB>>>(erow, ecol);        // launch 2

    // Branch A (capture stream): cast + GEMM1 (launch 4 = profiled slot)
    const size_t ncast4 = (size_t)NN * FIN / 4 + (size_t)FIN * DIMF / 4;
    k_xcast<<<(unsigned)((ncast4 + 255) / 256), 256, 0, s0>>>(x, W1); // launch 3
    dim3 g1(DIMF / 128, (NN + 127) / 128);
    k_gemm1<<<g1, 256, 0, s0>>>(b1);                              // launch 4

    // Branch B continued
    k_scan_part<<<NBLK, 1024, 0, sB>>>();
    k_scan_bsum<<<1, 64, 0, sB>>>();
    k_scan_add<<<NBLK, 1024, 0, sB>>>();
    k_scatter<<<(NE + 255) / 256, 256, 0, sB>>>(erow, ecol);
    k_wc16<<<(HDIM * NCLS + 255) / 256, 256, 0, sB>>>(W2);

    // ---- join ----
    cudaEventRecord(evJoin, sB);
    cudaStreamWaitEvent(s0, evJoin, 0);

    // Serial tail on capture stream
    k_spmm16<1><<<NN, 64, 0, s0>>>();
    k_spmm16<2><<<NN, 64, 0, s0>>>();
    k_gemm2<<<(NN + 127) / 128, 128, 0, s0>>>(b2, out);
}